// round 1
// baseline (speedup 1.0000x reference)
#include <cuda_runtime.h>
#include <cstdint>

// Problem constants (fixed shapes from reference)
#define HEADS   16
#define HDIM    128
#define EMB     2048
#define EMB3    6144
#define SEQ     2048
#define BATCH   2
#define MROWS   (BATCH*SEQ)        // 4096

// Scratch (allocation-free rule: __device__ globals)
__device__ float g_q[(size_t)BATCH*HEADS*SEQ*HDIM];
__device__ float g_k[(size_t)BATCH*HEADS*SEQ*HDIM];
__device__ float g_v[(size_t)BATCH*HEADS*SEQ*HDIM];
__device__ float g_att[(size_t)MROWS*EMB];

// ---------- packed f32x2 helpers (FFMA2: PTX-only pattern, 2x fp32 rate) ----------
__device__ __forceinline__ unsigned long long pk2(float lo, float hi) {
    unsigned long long r;
    asm("mov.b64 %0, {%1, %2};" : "=l"(r) : "f"(lo), "f"(hi));
    return r;
}
__device__ __forceinline__ void unpk2(unsigned long long v, float& lo, float& hi) {
    asm("mov.b64 {%0, %1}, %2;" : "=f"(lo), "=f"(hi) : "l"(v));
}
__device__ __forceinline__ unsigned long long fma2(unsigned long long a,
                                                   unsigned long long b,
                                                   unsigned long long c) {
    unsigned long long d;
    asm("fma.rn.f32x2 %0, %1, %2, %3;" : "=l"(d) : "l"(a), "l"(b), "l"(c));
    return d;
}
__device__ __forceinline__ unsigned long long mul2(unsigned long long a,
                                                   unsigned long long b) {
    unsigned long long d;
    asm("mul.rn.f32x2 %0, %1, %2;" : "=l"(d) : "l"(a), "l"(b));
    return d;
}

// =====================================================================
// SGEMM: C[M,N] = A[M,K] * B[N,K]^T   (both row-major, K contiguous)
// 128x128 block tile, BK=8, 256 threads, 8x8 register microtile, f32x2.
// MODE 0: epilogue scatters into g_q/g_k/g_v as [B,H,S,D]
// MODE 1: A is g_att (internal), epilogue writes C directly
// =====================================================================
template<int MODE>
__global__ void __launch_bounds__(256) sgemm_kernel(
    const float* __restrict__ A, const float* __restrict__ Bw,
    float* __restrict__ C, int M, int N, int K)
{
    __shared__ float As[8][128];
    __shared__ float Bs[8][128];

    const float* Ap = (MODE == 1) ? (const float*)g_att : A;

    int tid = threadIdx.x;
    int bm = blockIdx.y * 128;
    int bn = blockIdx.x * 128;

    int lr = tid >> 1;            // 0..127 : tile row for loads
    int lk = (tid & 1) << 2;      // 0 or 4 : k-quad for loads
    const float* Ag = Ap + (size_t)(bm + lr) * K + lk;
    const float* Bg = Bw + (size_t)(bn + lr) * K + lk;

    int tr = (tid >> 4) << 3;     // 0..120 : microtile row base
    int tc = (tid & 15) << 3;     // 0..120 : microtile col base

    unsigned long long acc[8][4];
#pragma unroll
    for (int i = 0; i < 8; i++)
#pragma unroll
        for (int j = 0; j < 4; j++) acc[i][j] = 0ULL;

    for (int k0 = 0; k0 < K; k0 += 8) {
        float4 av = *(const float4*)(Ag + k0);
        float4 bv = *(const float4*)(Bg + k0);
        As[lk + 0][lr] = av.x; As[lk + 1][lr] = av.y;
        As[lk + 2][lr] = av.z; As[lk + 3][lr] = av.w;
        Bs[lk + 0][lr] = bv.x; Bs[lk + 1][lr] = bv.y;
        Bs[lk + 2][lr] = bv.z; Bs[lk + 3][lr] = bv.w;
        __syncthreads();

#pragma unroll
        for (int kk = 0; kk < 8; kk++) {
            float4 a0 = *(const float4*)&As[kk][tr];
            float4 a1 = *(const float4*)&As[kk][tr + 4];
            unsigned long long b2[4];
#pragma unroll
            for (int j = 0; j < 4; j++)
                b2[j] = *(const unsigned long long*)&Bs[kk][tc + 2 * j];
            float ra[8] = {a0.x, a0.y, a0.z, a0.w, a1.x, a1.y, a1.z, a1.w};
#pragma unroll
            for (int i = 0; i < 8; i++) {
                unsigned long long ai = pk2(ra[i], ra[i]);
#pragma unroll
                for (int j = 0; j < 4; j++)
                    acc[i][j] = fma2(ai, b2[j], acc[i][j]);
            }
        }
        __syncthreads();
    }

    // unpack accumulators
    float c[8][8];
#pragma unroll
    for (int i = 0; i < 8; i++)
#pragma unroll
        for (int j = 0; j < 4; j++)
            unpk2(acc[i][j], c[i][2 * j], c[i][2 * j + 1]);

    if (MODE == 0) {
        // N block of 128 lies entirely inside one (which, head): 2048%128==0
        int which = bn >> 11;              // 0=q,1=k,2=v
        int hh    = (bn >> 7) & (HEADS - 1);
        int b     = bm >> 11;              // row block inside one batch (2048%128==0)
        int sBase = (bm & (SEQ - 1)) + tr;
        float* base = (which == 0 ? g_q : which == 1 ? g_k : g_v)
                      + ((size_t)(b * HEADS + hh)) * SEQ * HDIM;
#pragma unroll
        for (int i = 0; i < 8; i++) {
            float* dst = base + (size_t)(sBase + i) * HDIM + tc;
            *(float4*)(dst)     = make_float4(c[i][0], c[i][1], c[i][2], c[i][3]);
            *(float4*)(dst + 4) = make_float4(c[i][4], c[i][5], c[i][6], c[i][7]);
        }
    } else {
        float* dst = C + (size_t)(bm + tr) * N + bn + tc;
#pragma unroll
        for (int i = 0; i < 8; i++) {
            *(float4*)(dst + (size_t)i * N)     = make_float4(c[i][0], c[i][1], c[i][2], c[i][3]);
            *(float4*)(dst + (size_t)i * N + 4) = make_float4(c[i][4], c[i][5], c[i][6], c[i][7]);
        }
    }
}

// =====================================================================
// Flash attention (fp32, causal). One block = (q-tile of 64, head, batch).
// Br=Bc=64, 256 threads. Online softmax. f32x2 packed FMA in both matmuls.
// =====================================================================
#define BR  64
#define BC  64
#define SST 65   // padded score row stride (bank-conflict mitigation)

// smem floats: Q(64*128) K(64*128) V(64*128) S(64*65) m/l/alpha(3*64) pmax/psum(2*256)
#define ATTN_SMEM_FLOATS (3*64*128 + 64*SST + 3*64 + 2*256)
#define ATTN_SMEM_BYTES  (ATTN_SMEM_FLOATS * 4)

__global__ void __launch_bounds__(256) attn_kernel()
{
    extern __shared__ float sm[];
    float* Qs      = sm;                 // [64][128]
    float* Ks      = Qs + 64 * 128;      // [64][128]
    float* Vs      = Ks + 64 * 128;      // [64][128]
    float* Ss      = Vs + 64 * 128;      // [64][SST]
    float* m_s     = Ss + 64 * SST;      // [64]
    float* l_s     = m_s + 64;           // [64]
    float* alpha_s = l_s + 64;           // [64]
    float* pmax    = alpha_s + 64;       // [64][4]
    float* psum    = pmax + 256;         // [64][4]

    int t  = threadIdx.x;
    int qt = blockIdx.x, h = blockIdx.y, b = blockIdx.z;
    int q0 = qt * BR;
    size_t headBase = ((size_t)(b * HEADS + h)) * SEQ * HDIM;

    // load Q tile (flat float4 copy; layouts identical)
    {
        const float4* src = (const float4*)(g_q + headBase + (size_t)q0 * HDIM);
        float4* dst = (float4*)Qs;
#pragma unroll
        for (int it = 0; it < 8; it++) dst[t + it * 256] = src[t + it * 256];
    }
    if (t < 64) { m_s[t] = -1e30f; l_s[t] = 0.f; }

    // stage A ids: 16x16 grid, 4x4 score microtile
    int war = (t >> 4) << 2;     // score row base
    int wac = (t & 15) << 2;     // score col base
    // stage B ids
    int rB = t >> 2; int segB = t & 3; int cB = segB << 4;
    // stage C ids: 4 rows x 8 d per thread
    int rc0 = (t & 15) << 2;
    int d0  = (t >> 4) << 3;

    unsigned long long accO[4][4];
#pragma unroll
    for (int i = 0; i < 4; i++)
#pragma unroll
        for (int j = 0; j < 4; j++) accO[i][j] = 0ULL;

    const float scale = 0.08838834764831845f;   // 1/sqrt(128)

    for (int kt = 0; kt <= qt; kt++) {
        __syncthreads();  // protect Ks/Vs/Ss from previous iteration readers
        {
            const float4* ks = (const float4*)(g_k + headBase + (size_t)(kt * BC) * HDIM);
            const float4* vs = (const float4*)(g_v + headBase + (size_t)(kt * BC) * HDIM);
            float4* kd = (float4*)Ks; float4* vd = (float4*)Vs;
#pragma unroll
            for (int it = 0; it < 8; it++) {
                kd[t + it * 256] = ks[t + it * 256];
                vd[t + it * 256] = vs[t + it * 256];
            }
        }
        __syncthreads();

        // ---- stage A: S = Q K^T (f32x2 pairs over d, horizontal add at end)
        {
            unsigned long long acc[4][4];
#pragma unroll
            for (int i = 0; i < 4; i++)
#pragma unroll
                for (int j = 0; j < 4; j++) acc[i][j] = 0ULL;

#pragma unroll 8
            for (int d = 0; d < HDIM; d += 2) {
                unsigned long long q2[4], k2[4];
#pragma unroll
                for (int i = 0; i < 4; i++)
                    q2[i] = *(const unsigned long long*)&Qs[(war + i) * HDIM + d];
#pragma unroll
                for (int j = 0; j < 4; j++)
                    k2[j] = *(const unsigned long long*)&Ks[(wac + j) * HDIM + d];
#pragma unroll
                for (int i = 0; i < 4; i++)
#pragma unroll
                    for (int j = 0; j < 4; j++)
                        acc[i][j] = fma2(q2[i], k2[j], acc[i][j]);
            }
            bool diag = (kt == qt);
#pragma unroll
            for (int i = 0; i < 4; i++)
#pragma unroll
                for (int j = 0; j < 4; j++) {
                    float lo, hi; unpk2(acc[i][j], lo, hi);
                    float s = (lo + hi) * scale;
                    if (diag && (wac + j) > (war + i)) s = -1e30f;
                    Ss[(war + i) * SST + (wac + j)] = s;
                }
        }
        __syncthreads();

        // ---- stage B: online softmax (scores -> probabilities in Ss)
        {
            float* srow = Ss + rB * SST;
            float pm = -1e30f;
#pragma unroll
            for (int c = 0; c < 16; c++) pm = fmaxf(pm, srow[cB + c]);
            pmax[(rB << 2) + segB] = pm;
            __syncthreads();

            float mt = fmaxf(fmaxf(pmax[rB << 2], pmax[(rB << 2) + 1]),
                             fmaxf(pmax[(rB << 2) + 2], pmax[(rB << 2) + 3]));
            float mo = m_s[rB];
            float mn = fmaxf(mo, mt);
            float ps = 0.f;
#pragma unroll
            for (int c = 0; c < 16; c++) {
                float p = __expf(srow[cB + c] - mn);
                srow[cB + c] = p;
                ps += p;
            }
            psum[(rB << 2) + segB] = ps;
            __syncthreads();

            if (segB == 0) {
                float alpha = __expf(mo - mn);
                l_s[rB] = l_s[rB] * alpha
                        + psum[rB << 2] + psum[(rB << 2) + 1]
                        + psum[(rB << 2) + 2] + psum[(rB << 2) + 3];
                m_s[rB] = mn;
                alpha_s[rB] = alpha;
            }
            __syncthreads();
        }

        // ---- stage C: O = alpha*O + P V  (f32x2 pairs over d)
#pragma unroll
        for (int i = 0; i < 4; i++) {
            float al = alpha_s[rc0 + i];
            unsigned long long a2 = pk2(al, al);
#pragma unroll
            for (int jp = 0; jp < 4; jp++) accO[i][jp] = mul2(accO[i][jp], a2);
        }
#pragma unroll 4
        for (int c = 0; c < BC; c++) {
            unsigned long long v2[4];
#pragma unroll
            for (int jp = 0; jp < 4; jp++)
                v2[jp] = *(const unsigned long long*)&Vs[c * HDIM + d0 + 2 * jp];
#pragma unroll
            for (int i = 0; i < 4; i++) {
                float p = Ss[(rc0 + i) * SST + c];
                unsigned long long p2 = pk2(p, p);
#pragma unroll
                for (int jp = 0; jp < 4; jp++)
                    accO[i][jp] = fma2(p2, v2[jp], accO[i][jp]);
            }
        }
    }

    // epilogue: normalize by l, write to g_att[B,S,E] layout
#pragma unroll
    for (int i = 0; i < 4; i++) {
        float inv = 1.0f / l_s[rc0 + i];
        float o[8];
#pragma unroll
        for (int jp = 0; jp < 4; jp++) unpk2(accO[i][jp], o[2 * jp], o[2 * jp + 1]);
#pragma unroll
        for (int k = 0; k < 8; k++) o[k] *= inv;
        size_t row = (size_t)(b * SEQ + q0 + rc0 + i);
        float* dst = g_att + row * EMB + h * HDIM + d0;
        *(float4*)(dst)     = make_float4(o[0], o[1], o[2], o[3]);
        *(float4*)(dst + 4) = make_float4(o[4], o[5], o[6], o[7]);
    }
}

// =====================================================================
// launch
// =====================================================================
extern "C" void kernel_launch(void* const* d_in, const int* in_sizes, int n_in,
                              void* d_out, int out_size)
{
    (void)in_sizes; (void)n_in; (void)out_size;
    const float* x     = (const float*)d_in[0];   // [B,S,E]
    const float* Wqkv  = (const float*)d_in[1];   // [3E,E]
    const float* Wproj = (const float*)d_in[2];   // [E,E]
    float* out = (float*)d_out;                   // [B,S,E]

    // 1) qkv = x @ Wqkv^T, scattered into g_q/g_k/g_v [B,H,S,D]
    dim3 g1(EMB3 / 128, MROWS / 128);
    sgemm_kernel<0><<<g1, 256>>>(x, Wqkv, nullptr, MROWS, EMB3, EMB);

    // 2) causal flash attention -> g_att [B,S,E]
    cudaFuncSetAttribute(attn_kernel,
                         cudaFuncAttributeMaxDynamicSharedMemorySize,
                         ATTN_SMEM_BYTES);
    dim3 g2(SEQ / BR, HEADS, BATCH);
    attn_kernel<<<g2, 256, ATTN_SMEM_BYTES>>>();

    // 3) out = g_att @ Wproj^T
    dim3 g3(EMB / 128, MROWS / 128);
    sgemm_kernel<1><<<g3, 256>>>(nullptr, Wproj, out, MROWS, EMB, EMB);
}

// round 2
// speedup vs baseline: 1.6114x; 1.6114x over previous
#include <cuda_runtime.h>
#include <cstdint>

// Problem constants (fixed shapes from reference)
#define HEADS   16
#define HDIM    128
#define EMB     2048
#define EMB3    6144
#define SEQ     2048
#define BATCH   2
#define MROWS   (BATCH*SEQ)        // 4096

// Scratch (allocation-free rule: __device__ globals)
__device__ float g_q[(size_t)BATCH*HEADS*SEQ*HDIM];
__device__ float g_k[(size_t)BATCH*HEADS*SEQ*HDIM];
__device__ float g_v[(size_t)BATCH*HEADS*SEQ*HDIM];
__device__ float g_att[(size_t)MROWS*EMB];

// ---------- packed f32x2 helpers (used by attention kernel) ----------
__device__ __forceinline__ unsigned long long pk2(float lo, float hi) {
    unsigned long long r;
    asm("mov.b64 %0, {%1, %2};" : "=l"(r) : "f"(lo), "f"(hi));
    return r;
}
__device__ __forceinline__ void unpk2(unsigned long long v, float& lo, float& hi) {
    asm("mov.b64 {%0, %1}, %2;" : "=f"(lo), "=f"(hi) : "l"(v));
}
__device__ __forceinline__ unsigned long long fma2(unsigned long long a,
                                                   unsigned long long b,
                                                   unsigned long long c) {
    unsigned long long d;
    asm("fma.rn.f32x2 %0, %1, %2, %3;" : "=l"(d) : "l"(a), "l"(b), "l"(c));
    return d;
}
__device__ __forceinline__ unsigned long long mul2(unsigned long long a,
                                                   unsigned long long b) {
    unsigned long long d;
    asm("mul.rn.f32x2 %0, %1, %2;" : "=l"(d) : "l"(a), "l"(b));
    return d;
}

// ---------- tf32 helpers ----------
__device__ __forceinline__ uint32_t f2tf32(float f) {
    uint32_t r;
    asm("cvt.rna.tf32.f32 %0, %1;" : "=r"(r) : "f"(f));
    return r;
}
__device__ __forceinline__ void mma_tf32(float* c, const uint32_t* a,
                                         uint32_t b0, uint32_t b1) {
    asm volatile(
        "mma.sync.aligned.m16n8k8.row.col.f32.tf32.tf32.f32 "
        "{%0,%1,%2,%3}, {%4,%5,%6,%7}, {%8,%9}, {%0,%1,%2,%3};"
        : "+f"(c[0]), "+f"(c[1]), "+f"(c[2]), "+f"(c[3])
        : "r"(a[0]), "r"(a[1]), "r"(a[2]), "r"(a[3]), "r"(b0), "r"(b1));
}

// =====================================================================
// TF32 tensor-core GEMM: C[M,N] = A[M,K] * B[N,K]^T  (row-major, K contig)
// 128x128x32 block, 256 threads (8 warps @ 64x32 warp tile, 4x4 frags of
// m16n8k8). Smem layout [row][32] with float4-quad xor swizzle
// (qd' = qd ^ (row&7)) -> conflict-free STS.128 staging and scalar frag LDS.
// MODE 0: epilogue scatters into g_q/g_k/g_v as [B,H,S,D]
// MODE 1: A is g_att (internal), epilogue writes C directly
// =====================================================================
#define GBM 128
#define GBN 128
#define GBK 32

template<int MODE>
__global__ void __launch_bounds__(256) sgemm_tf32_kernel(
    const float* __restrict__ A, const float* __restrict__ Bw,
    float* __restrict__ C, int M, int N, int K)
{
    __shared__ uint32_t As[GBM][GBK];
    __shared__ uint32_t Bs[GBN][GBK];

    const float* Ap = (MODE == 1) ? (const float*)g_att : A;

    const int tid  = threadIdx.x;
    const int warp = tid >> 5;
    const int lane = tid & 31;
    const int g    = lane >> 2;   // fragment group (0..7)
    const int q    = lane & 3;    // fragment quad-thread (0..3)

    const int bm = blockIdx.y * GBM;
    const int bn = blockIdx.x * GBN;
    const int wm = (warp >> 2) * 64;   // warp m-offset (0 or 64)
    const int wn = (warp & 3) * 32;    // warp n-offset (0,32,64,96)

    // staging ids: per pass p (0..3): row = p*32 + (tid>>3), quad = tid&7
    const int srow = tid >> 3;          // 0..31
    const int sqd  = tid & 7;           // 0..7
    const int sqd4 = sqd * 4;

    float acc[4][4][4];
#pragma unroll
    for (int i = 0; i < 4; i++)
#pragma unroll
        for (int j = 0; j < 4; j++)
#pragma unroll
            for (int e = 0; e < 4; e++) acc[i][j][e] = 0.f;

    // prefetch first tile into registers
    float4 pa[4], pb[4];
#pragma unroll
    for (int p = 0; p < 4; p++) {
        int r = p * 32 + srow;
        pa[p] = *(const float4*)(Ap + (size_t)(bm + r) * K + sqd4);
        pb[p] = *(const float4*)(Bw + (size_t)(bn + r) * K + sqd4);
    }

    for (int k0 = 0; k0 < K; k0 += GBK) {
        __syncthreads();   // previous compute done before overwrite
        // store staged tile (cvt to tf32, STS.128, xor-swizzled quad)
#pragma unroll
        for (int p = 0; p < 4; p++) {
            int r = p * 32 + srow;
            int qd = sqd ^ (r & 7);
            uint4 va = make_uint4(f2tf32(pa[p].x), f2tf32(pa[p].y),
                                  f2tf32(pa[p].z), f2tf32(pa[p].w));
            uint4 vb = make_uint4(f2tf32(pb[p].x), f2tf32(pb[p].y),
                                  f2tf32(pb[p].z), f2tf32(pb[p].w));
            *(uint4*)&As[r][qd * 4] = va;
            *(uint4*)&Bs[r][qd * 4] = vb;
        }
        __syncthreads();

        // prefetch next tile
        if (k0 + GBK < K) {
#pragma unroll
            for (int p = 0; p < 4; p++) {
                int r = p * 32 + srow;
                pa[p] = *(const float4*)(Ap + (size_t)(bm + r) * K + k0 + GBK + sqd4);
                pb[p] = *(const float4*)(Bw + (size_t)(bn + r) * K + k0 + GBK + sqd4);
            }
        }

        // compute: 4 k8 substeps
#pragma unroll
        for (int ks = 0; ks < 4; ks++) {
            const int qa0 = ((2 * ks)     ^ g) * 4 + q;  // quad col for a0/a1/b0
            const int qa1 = ((2 * ks + 1) ^ g) * 4 + q;  // quad col for a2/a3/b1
            uint32_t a[4][4];
#pragma unroll
            for (int i = 0; i < 4; i++) {
                int m0 = wm + i * 16 + g;
                a[i][0] = As[m0][qa0];
                a[i][1] = As[m0 + 8][qa0];
                a[i][2] = As[m0][qa1];
                a[i][3] = As[m0 + 8][qa1];
            }
#pragma unroll
            for (int j = 0; j < 4; j++) {
                int n0 = wn + j * 8 + g;
                uint32_t b0 = Bs[n0][qa0];
                uint32_t b1 = Bs[n0][qa1];
#pragma unroll
                for (int i = 0; i < 4; i++)
                    mma_tf32(acc[i][j], a[i], b0, b1);
            }
        }
    }

    // epilogue: fragment (i,j): rows bm+wm+i*16+{g, g+8}, cols bn+wn+j*8+{2q,2q+1}
#pragma unroll
    for (int i = 0; i < 4; i++) {
#pragma unroll
        for (int j = 0; j < 4; j++) {
            int r0 = bm + wm + i * 16 + g;
            int n0 = bn + wn + j * 8 + 2 * q;
            if (MODE == 0) {
                int which = n0 >> 11;
                int hh    = (n0 >> 7) & (HEADS - 1);
                int d     = n0 & (HDIM - 1);
                int b     = r0 >> 11;
                float* base = (which == 0 ? g_q : which == 1 ? g_k : g_v)
                              + ((size_t)(b * HEADS + hh)) * SEQ * HDIM;
                int s0 = r0 & (SEQ - 1);
                *(float2*)&base[(size_t)s0 * HDIM + d] =
                    make_float2(acc[i][j][0], acc[i][j][1]);
                *(float2*)&base[(size_t)(s0 + 8) * HDIM + d] =
                    make_float2(acc[i][j][2], acc[i][j][3]);
            } else {
                *(float2*)(C + (size_t)r0 * N + n0) =
                    make_float2(acc[i][j][0], acc[i][j][1]);
                *(float2*)(C + (size_t)(r0 + 8) * N + n0) =
                    make_float2(acc[i][j][2], acc[i][j][3]);
            }
        }
    }
}

// =====================================================================
// Flash attention (fp32, causal). One block = (q-tile of 64, head, batch).
// Br=Bc=64, 256 threads. Online softmax. f32x2 packed FMA in both matmuls.
// =====================================================================
#define BR  64
#define BC  64
#define SST 65   // padded score row stride (bank-conflict mitigation)

// smem floats: Q(64*128) K(64*128) V(64*128) S(64*65) m/l/alpha(3*64) pmax/psum(2*256)
#define ATTN_SMEM_FLOATS (3*64*128 + 64*SST + 3*64 + 2*256)
#define ATTN_SMEM_BYTES  (ATTN_SMEM_FLOATS * 4)

__global__ void __launch_bounds__(256) attn_kernel()
{
    extern __shared__ float sm[];
    float* Qs      = sm;                 // [64][128]
    float* Ks      = Qs + 64 * 128;      // [64][128]
    float* Vs      = Ks + 64 * 128;      // [64][128]
    float* Ss      = Vs + 64 * 128;      // [64][SST]
    float* m_s     = Ss + 64 * SST;      // [64]
    float* l_s     = m_s + 64;           // [64]
    float* alpha_s = l_s + 64;           // [64]
    float* pmax    = alpha_s + 64;       // [64][4]
    float* psum    = pmax + 256;         // [64][4]

    int t  = threadIdx.x;
    int qt = blockIdx.x, h = blockIdx.y, b = blockIdx.z;
    int q0 = qt * BR;
    size_t headBase = ((size_t)(b * HEADS + h)) * SEQ * HDIM;

    // load Q tile (flat float4 copy; layouts identical)
    {
        const float4* src = (const float4*)(g_q + headBase + (size_t)q0 * HDIM);
        float4* dst = (float4*)Qs;
#pragma unroll
        for (int it = 0; it < 8; it++) dst[t + it * 256] = src[t + it * 256];
    }
    if (t < 64) { m_s[t] = -1e30f; l_s[t] = 0.f; }

    // stage A ids: 16x16 grid, 4x4 score microtile
    int war = (t >> 4) << 2;     // score row base
    int wac = (t & 15) << 2;     // score col base
    // stage B ids
    int rB = t >> 2; int segB = t & 3; int cB = segB << 4;
    // stage C ids: 4 rows x 8 d per thread
    int rc0 = (t & 15) << 2;
    int d0  = (t >> 4) << 3;

    unsigned long long accO[4][4];
#pragma unroll
    for (int i = 0; i < 4; i++)
#pragma unroll
        for (int j = 0; j < 4; j++) accO[i][j] = 0ULL;

    const float scale = 0.08838834764831845f;   // 1/sqrt(128)

    for (int kt = 0; kt <= qt; kt++) {
        __syncthreads();  // protect Ks/Vs/Ss from previous iteration readers
        {
            const float4* ks = (const float4*)(g_k + headBase + (size_t)(kt * BC) * HDIM);
            const float4* vs = (const float4*)(g_v + headBase + (size_t)(kt * BC) * HDIM);
            float4* kd = (float4*)Ks; float4* vd = (float4*)Vs;
#pragma unroll
            for (int it = 0; it < 8; it++) {
                kd[t + it * 256] = ks[t + it * 256];
                vd[t + it * 256] = vs[t + it * 256];
            }
        }
        __syncthreads();

        // ---- stage A: S = Q K^T (f32x2 pairs over d, horizontal add at end)
        {
            unsigned long long acc[4][4];
#pragma unroll
            for (int i = 0; i < 4; i++)
#pragma unroll
                for (int j = 0; j < 4; j++) acc[i][j] = 0ULL;

#pragma unroll 8
            for (int d = 0; d < HDIM; d += 2) {
                unsigned long long q2[4], k2[4];
#pragma unroll
                for (int i = 0; i < 4; i++)
                    q2[i] = *(const unsigned long long*)&Qs[(war + i) * HDIM + d];
#pragma unroll
                for (int j = 0; j < 4; j++)
                    k2[j] = *(const unsigned long long*)&Ks[(wac + j) * HDIM + d];
#pragma unroll
                for (int i = 0; i < 4; i++)
#pragma unroll
                    for (int j = 0; j < 4; j++)
                        acc[i][j] = fma2(q2[i], k2[j], acc[i][j]);
            }
            bool diag = (kt == qt);
#pragma unroll
            for (int i = 0; i < 4; i++)
#pragma unroll
                for (int j = 0; j < 4; j++) {
                    float lo, hi; unpk2(acc[i][j], lo, hi);
                    float s = (lo + hi) * scale;
                    if (diag && (wac + j) > (war + i)) s = -1e30f;
                    Ss[(war + i) * SST + (wac + j)] = s;
                }
        }
        __syncthreads();

        // ---- stage B: online softmax (scores -> probabilities in Ss)
        {
            float* srow = Ss + rB * SST;
            float pm = -1e30f;
#pragma unroll
            for (int c = 0; c < 16; c++) pm = fmaxf(pm, srow[cB + c]);
            pmax[(rB << 2) + segB] = pm;
            __syncthreads();

            float mt = fmaxf(fmaxf(pmax[rB << 2], pmax[(rB << 2) + 1]),
                             fmaxf(pmax[(rB << 2) + 2], pmax[(rB << 2) + 3]));
            float mo = m_s[rB];
            float mn = fmaxf(mo, mt);
            float ps = 0.f;
#pragma unroll
            for (int c = 0; c < 16; c++) {
                float p = __expf(srow[cB + c] - mn);
                srow[cB + c] = p;
                ps += p;
            }
            psum[(rB << 2) + segB] = ps;
            __syncthreads();

            if (segB == 0) {
                float alpha = __expf(mo - mn);
                l_s[rB] = l_s[rB] * alpha
                        + psum[rB << 2] + psum[(rB << 2) + 1]
                        + psum[(rB << 2) + 2] + psum[(rB << 2) + 3];
                m_s[rB] = mn;
                alpha_s[rB] = alpha;
            }
            __syncthreads();
        }

        // ---- stage C: O = alpha*O + P V  (f32x2 pairs over d)
#pragma unroll
        for (int i = 0; i < 4; i++) {
            float al = alpha_s[rc0 + i];
            unsigned long long a2 = pk2(al, al);
#pragma unroll
            for (int jp = 0; jp < 4; jp++) accO[i][jp] = mul2(accO[i][jp], a2);
        }
#pragma unroll 4
        for (int c = 0; c < BC; c++) {
            unsigned long long v2[4];
#pragma unroll
            for (int jp = 0; jp < 4; jp++)
                v2[jp] = *(const unsigned long long*)&Vs[c * HDIM + d0 + 2 * jp];
#pragma unroll
            for (int i = 0; i < 4; i++) {
                float p = Ss[(rc0 + i) * SST + c];
                unsigned long long p2 = pk2(p, p);
#pragma unroll
                for (int jp = 0; jp < 4; jp++)
                    accO[i][jp] = fma2(p2, v2[jp], accO[i][jp]);
            }
        }
    }

    // epilogue: normalize by l, write to g_att[B,S,E] layout
#pragma unroll
    for (int i = 0; i < 4; i++) {
        float inv = 1.0f / l_s[rc0 + i];
        float o[8];
#pragma unroll
        for (int jp = 0; jp < 4; jp++) unpk2(accO[i][jp], o[2 * jp], o[2 * jp + 1]);
#pragma unroll
        for (int k = 0; k < 8; k++) o[k] *= inv;
        size_t row = (size_t)(b * SEQ + q0 + rc0 + i);
        float* dst = g_att + row * EMB + h * HDIM + d0;
        *(float4*)(dst)     = make_float4(o[0], o[1], o[2], o[3]);
        *(float4*)(dst + 4) = make_float4(o[4], o[5], o[6], o[7]);
    }
}

// =====================================================================
// launch
// =====================================================================
extern "C" void kernel_launch(void* const* d_in, const int* in_sizes, int n_in,
                              void* d_out, int out_size)
{
    (void)in_sizes; (void)n_in; (void)out_size;
    const float* x     = (const float*)d_in[0];   // [B,S,E]
    const float* Wqkv  = (const float*)d_in[1];   // [3E,E]
    const float* Wproj = (const float*)d_in[2];   // [E,E]
    float* out = (float*)d_out;                   // [B,S,E]

    // 1) qkv = x @ Wqkv^T, scattered into g_q/g_k/g_v [B,H,S,D]
    dim3 g1(EMB3 / GBN, MROWS / GBM);
    sgemm_tf32_kernel<0><<<g1, 256>>>(x, Wqkv, nullptr, MROWS, EMB3, EMB);

    // 2) causal flash attention -> g_att [B,S,E]
    cudaFuncSetAttribute(attn_kernel,
                         cudaFuncAttributeMaxDynamicSharedMemorySize,
                         ATTN_SMEM_BYTES);
    dim3 g2(SEQ / BR, HEADS, BATCH);
    attn_kernel<<<g2, 256, ATTN_SMEM_BYTES>>>();

    // 3) out = g_att @ Wproj^T
    dim3 g3(EMB / GBN, MROWS / GBM);
    sgemm_tf32_kernel<1><<<g3, 256>>>(nullptr, Wproj, out, MROWS, EMB, EMB);
}

// round 3
// speedup vs baseline: 4.2582x; 2.6425x over previous
#include <cuda_runtime.h>
#include <cstdint>

// Problem constants (fixed shapes from reference)
#define HEADS   16
#define HDIM    128
#define EMB     2048
#define EMB3    6144
#define SEQ     2048
#define BATCH   2
#define MROWS   (BATCH*SEQ)        // 4096

// Scratch (allocation-free rule: __device__ globals)
__device__ float g_q[(size_t)BATCH*HEADS*SEQ*HDIM];
__device__ float g_k[(size_t)BATCH*HEADS*SEQ*HDIM];
__device__ float g_v[(size_t)BATCH*HEADS*SEQ*HDIM];
__device__ float g_att[(size_t)MROWS*EMB];

// ---------- tf32 helpers ----------
__device__ __forceinline__ uint32_t f2tf32(float f) {
    uint32_t r;
    asm("cvt.rna.tf32.f32 %0, %1;" : "=r"(r) : "f"(f));
    return r;
}
__device__ __forceinline__ void mma_tf32(float* c, const uint32_t* a,
                                         uint32_t b0, uint32_t b1) {
    asm volatile(
        "mma.sync.aligned.m16n8k8.row.col.f32.tf32.tf32.f32 "
        "{%0,%1,%2,%3}, {%4,%5,%6,%7}, {%8,%9}, {%0,%1,%2,%3};"
        : "+f"(c[0]), "+f"(c[1]), "+f"(c[2]), "+f"(c[3])
        : "r"(a[0]), "r"(a[1]), "r"(a[2]), "r"(a[3]), "r"(b0), "r"(b1));
}

// =====================================================================
// TF32 tensor-core GEMM: C[M,N] = A[M,K] * B[N,K]^T  (row-major, K contig)
// 128x128x32 block, 256 threads (8 warps @ 64x32 warp tile, 4x4 frags of
// m16n8k8). Smem layout [row][32] with float4-quad xor swizzle.
// MODE 0: epilogue scatters into g_q/g_k/g_v as [B,H,S,D]
// MODE 1: A is g_att (internal), epilogue writes C directly
// =====================================================================
#define GBM 128
#define GBN 128
#define GBK 32

template<int MODE>
__global__ void __launch_bounds__(256) sgemm_tf32_kernel(
    const float* __restrict__ A, const float* __restrict__ Bw,
    float* __restrict__ C, int M, int N, int K)
{
    __shared__ uint32_t As[GBM][GBK];
    __shared__ uint32_t Bs[GBN][GBK];

    const float* Ap = (MODE == 1) ? (const float*)g_att : A;

    const int tid  = threadIdx.x;
    const int warp = tid >> 5;
    const int lane = tid & 31;
    const int g    = lane >> 2;   // fragment group (0..7)
    const int q    = lane & 3;    // fragment quad-thread (0..3)

    const int bm = blockIdx.y * GBM;
    const int bn = blockIdx.x * GBN;
    const int wm = (warp >> 2) * 64;   // warp m-offset (0 or 64)
    const int wn = (warp & 3) * 32;    // warp n-offset (0,32,64,96)

    const int srow = tid >> 3;          // 0..31
    const int sqd  = tid & 7;           // 0..7
    const int sqd4 = sqd * 4;

    float acc[4][4][4];
#pragma unroll
    for (int i = 0; i < 4; i++)
#pragma unroll
        for (int j = 0; j < 4; j++)
#pragma unroll
            for (int e = 0; e < 4; e++) acc[i][j][e] = 0.f;

    float4 pa[4], pb[4];
#pragma unroll
    for (int p = 0; p < 4; p++) {
        int r = p * 32 + srow;
        pa[p] = *(const float4*)(Ap + (size_t)(bm + r) * K + sqd4);
        pb[p] = *(const float4*)(Bw + (size_t)(bn + r) * K + sqd4);
    }

    for (int k0 = 0; k0 < K; k0 += GBK) {
        __syncthreads();
#pragma unroll
        for (int p = 0; p < 4; p++) {
            int r = p * 32 + srow;
            int qd = sqd ^ (r & 7);
            uint4 va = make_uint4(f2tf32(pa[p].x), f2tf32(pa[p].y),
                                  f2tf32(pa[p].z), f2tf32(pa[p].w));
            uint4 vb = make_uint4(f2tf32(pb[p].x), f2tf32(pb[p].y),
                                  f2tf32(pb[p].z), f2tf32(pb[p].w));
            *(uint4*)&As[r][qd * 4] = va;
            *(uint4*)&Bs[r][qd * 4] = vb;
        }
        __syncthreads();

        if (k0 + GBK < K) {
#pragma unroll
            for (int p = 0; p < 4; p++) {
                int r = p * 32 + srow;
                pa[p] = *(const float4*)(Ap + (size_t)(bm + r) * K + k0 + GBK + sqd4);
                pb[p] = *(const float4*)(Bw + (size_t)(bn + r) * K + k0 + GBK + sqd4);
            }
        }

#pragma unroll
        for (int ks = 0; ks < 4; ks++) {
            const int qa0 = ((2 * ks)     ^ g) * 4 + q;
            const int qa1 = ((2 * ks + 1) ^ g) * 4 + q;
            uint32_t a[4][4];
#pragma unroll
            for (int i = 0; i < 4; i++) {
                int m0 = wm + i * 16 + g;
                a[i][0] = As[m0][qa0];
                a[i][1] = As[m0 + 8][qa0];
                a[i][2] = As[m0][qa1];
                a[i][3] = As[m0 + 8][qa1];
            }
#pragma unroll
            for (int j = 0; j < 4; j++) {
                int n0 = wn + j * 8 + g;
                uint32_t b0 = Bs[n0][qa0];
                uint32_t b1 = Bs[n0][qa1];
#pragma unroll
                for (int i = 0; i < 4; i++)
                    mma_tf32(acc[i][j], a[i], b0, b1);
            }
        }
    }

#pragma unroll
    for (int i = 0; i < 4; i++) {
#pragma unroll
        for (int j = 0; j < 4; j++) {
            int r0 = bm + wm + i * 16 + g;
            int n0 = bn + wn + j * 8 + 2 * q;
            if (MODE == 0) {
                int which = n0 >> 11;
                int hh    = (n0 >> 7) & (HEADS - 1);
                int d     = n0 & (HDIM - 1);
                int b     = r0 >> 11;
                float* base = (which == 0 ? g_q : which == 1 ? g_k : g_v)
                              + ((size_t)(b * HEADS + hh)) * SEQ * HDIM;
                int s0 = r0 & (SEQ - 1);
                *(float2*)&base[(size_t)s0 * HDIM + d] =
                    make_float2(acc[i][j][0], acc[i][j][1]);
                *(float2*)&base[(size_t)(s0 + 8) * HDIM + d] =
                    make_float2(acc[i][j][2], acc[i][j][3]);
            } else {
                *(float2*)(C + (size_t)r0 * N + n0) =
                    make_float2(acc[i][j][0], acc[i][j][1]);
                *(float2*)(C + (size_t)(r0 + 8) * N + n0) =
                    make_float2(acc[i][j][2], acc[i][j][3]);
            }
        }
    }
}

// =====================================================================
// TF32 tensor-core flash attention (causal).
// Block = (64 q-rows, head, batch), 128 threads = 4 warps x 16-row tiles.
// Q frags pre-scaled+tf32 in registers; K/V tf32 in smem (stride 132);
// softmax fp32 in registers with q-quad shfl reductions; P via warp-private
// smem tile (stride 68) to re-enter MMA A-fragment layout.
// =====================================================================
#define AT_BR 64
#define AT_BC 64
#define KST   132
#define PST   68
// smem words: K + V + P
#define ATTN_SMEM_WORDS (2 * AT_BC * KST + AT_BR * PST)
#define ATTN_SMEM_BYTES (ATTN_SMEM_WORDS * 4)

__global__ void __launch_bounds__(128) attn_tf32_kernel()
{
    extern __shared__ uint32_t smw[];
    uint32_t* Ks = smw;                       // [64][KST] tf32 (also Q staging)
    uint32_t* Vs = Ks + AT_BC * KST;          // [64][KST] tf32
    uint32_t* Ps = Vs + AT_BC * KST;          // [64][PST] tf32

    const int t    = threadIdx.x;
    const int warp = t >> 5;
    const int lane = t & 31;
    const int g    = lane >> 2;
    const int q    = lane & 3;
    const int wrow = warp * 16;

    const int qt = blockIdx.x, h = blockIdx.y, b = blockIdx.z;
    const int q0 = qt * AT_BR;
    const size_t headBase = ((size_t)(b * HEADS + h)) * SEQ * HDIM;
    const float scale = 0.08838834764831845f;   // 1/sqrt(128)

    // ---- stage Q (scaled -> tf32) into Ks, then build register frags ----
    {
        const float4* Qg = (const float4*)(g_q + headBase + (size_t)q0 * HDIM);
#pragma unroll
        for (int i = 0; i < 16; i++) {
            int idx = t + i * 128;
            int row = idx >> 5, c = idx & 31;
            float4 v = Qg[idx];
            uint4 u = make_uint4(f2tf32(v.x * scale), f2tf32(v.y * scale),
                                 f2tf32(v.z * scale), f2tf32(v.w * scale));
            *(uint4*)&Ks[row * KST + c * 4] = u;
        }
    }
    __syncthreads();

    uint32_t qf[16][4];
#pragma unroll
    for (int ks = 0; ks < 16; ks++) {
        qf[ks][0] = Ks[(wrow + g)     * KST + ks * 8 + q];
        qf[ks][1] = Ks[(wrow + g + 8) * KST + ks * 8 + q];
        qf[ks][2] = Ks[(wrow + g)     * KST + ks * 8 + q + 4];
        qf[ks][3] = Ks[(wrow + g + 8) * KST + ks * 8 + q + 4];
    }

    float accO[16][4];
#pragma unroll
    for (int n = 0; n < 16; n++)
#pragma unroll
        for (int e = 0; e < 4; e++) accO[n][e] = 0.f;

    float m0r = -1e30f, m1r = -1e30f;   // row maxes (rows g, g+8)
    float l0r = 0.f, l1r = 0.f;         // row sums

    for (int kt = 0; kt <= qt; kt++) {
        __syncthreads();   // Q frags built / previous tile's K,V reads done
        {
            const float4* Kg = (const float4*)(g_k + headBase + (size_t)(kt * AT_BC) * HDIM);
            const float4* Vg = (const float4*)(g_v + headBase + (size_t)(kt * AT_BC) * HDIM);
#pragma unroll
            for (int i = 0; i < 16; i++) {
                int idx = t + i * 128;
                int row = idx >> 5, c = idx & 31;
                float4 kv = Kg[idx];
                float4 vv = Vg[idx];
                *(uint4*)&Ks[row * KST + c * 4] =
                    make_uint4(f2tf32(kv.x), f2tf32(kv.y), f2tf32(kv.z), f2tf32(kv.w));
                *(uint4*)&Vs[row * KST + c * 4] =
                    make_uint4(f2tf32(vv.x), f2tf32(vv.y), f2tf32(vv.z), f2tf32(vv.w));
            }
        }
        __syncthreads();

        // ---- S = Q K^T (scaled) ----
        float sc[8][4];
#pragma unroll
        for (int n = 0; n < 8; n++)
#pragma unroll
            for (int e = 0; e < 4; e++) sc[n][e] = 0.f;

#pragma unroll
        for (int ks = 0; ks < 16; ks++) {
#pragma unroll
            for (int n = 0; n < 8; n++) {
                uint32_t b0 = Ks[(n * 8 + g) * KST + ks * 8 + q];
                uint32_t b1 = Ks[(n * 8 + g) * KST + ks * 8 + q + 4];
                mma_tf32(sc[n], qf[ks], b0, b1);
            }
        }

        // ---- causal mask on diagonal tile ----
        if (kt == qt) {
            int r0 = wrow + g, r1 = wrow + g + 8;
#pragma unroll
            for (int n = 0; n < 8; n++) {
                int c0 = n * 8 + 2 * q, c1 = c0 + 1;
                if (c0 > r0) sc[n][0] = -1e30f;
                if (c1 > r0) sc[n][1] = -1e30f;
                if (c0 > r1) sc[n][2] = -1e30f;
                if (c1 > r1) sc[n][3] = -1e30f;
            }
        }

        // ---- online softmax (per-row, in-warp) ----
        float pm0 = -1e30f, pm1 = -1e30f;
#pragma unroll
        for (int n = 0; n < 8; n++) {
            pm0 = fmaxf(pm0, fmaxf(sc[n][0], sc[n][1]));
            pm1 = fmaxf(pm1, fmaxf(sc[n][2], sc[n][3]));
        }
        pm0 = fmaxf(pm0, __shfl_xor_sync(0xffffffffu, pm0, 1));
        pm0 = fmaxf(pm0, __shfl_xor_sync(0xffffffffu, pm0, 2));
        pm1 = fmaxf(pm1, __shfl_xor_sync(0xffffffffu, pm1, 1));
        pm1 = fmaxf(pm1, __shfl_xor_sync(0xffffffffu, pm1, 2));

        float mn0 = fmaxf(m0r, pm0);
        float mn1 = fmaxf(m1r, pm1);
        float al0 = __expf(m0r - mn0);
        float al1 = __expf(m1r - mn1);
        m0r = mn0; m1r = mn1;

        float ps0 = 0.f, ps1 = 0.f;
#pragma unroll
        for (int n = 0; n < 8; n++) {
            float p00 = __expf(sc[n][0] - mn0);
            float p01 = __expf(sc[n][1] - mn0);
            float p10 = __expf(sc[n][2] - mn1);
            float p11 = __expf(sc[n][3] - mn1);
            ps0 += p00 + p01;
            ps1 += p10 + p11;
            uint32_t* pr0 = &Ps[(wrow + g) * PST + n * 8 + 2 * q];
            uint32_t* pr1 = &Ps[(wrow + g + 8) * PST + n * 8 + 2 * q];
            pr0[0] = f2tf32(p00); pr0[1] = f2tf32(p01);
            pr1[0] = f2tf32(p10); pr1[1] = f2tf32(p11);
        }
        ps0 += __shfl_xor_sync(0xffffffffu, ps0, 1);
        ps0 += __shfl_xor_sync(0xffffffffu, ps0, 2);
        ps1 += __shfl_xor_sync(0xffffffffu, ps1, 1);
        ps1 += __shfl_xor_sync(0xffffffffu, ps1, 2);
        l0r = l0r * al0 + ps0;
        l1r = l1r * al1 + ps1;

        // rescale accumulators
#pragma unroll
        for (int n = 0; n < 16; n++) {
            accO[n][0] *= al0; accO[n][1] *= al0;
            accO[n][2] *= al1; accO[n][3] *= al1;
        }

        __syncwarp();   // P tile visible within warp

        // ---- O += P V ----
#pragma unroll
        for (int ks = 0; ks < 8; ks++) {
            uint32_t pa[4];
            pa[0] = Ps[(wrow + g)     * PST + ks * 8 + q];
            pa[1] = Ps[(wrow + g + 8) * PST + ks * 8 + q];
            pa[2] = Ps[(wrow + g)     * PST + ks * 8 + q + 4];
            pa[3] = Ps[(wrow + g + 8) * PST + ks * 8 + q + 4];
#pragma unroll
            for (int n = 0; n < 16; n++) {
                uint32_t b0 = Vs[(ks * 8 + q)     * KST + n * 8 + g];
                uint32_t b1 = Vs[(ks * 8 + q + 4) * KST + n * 8 + g];
                mma_tf32(accO[n], pa, b0, b1);
            }
        }
        __syncwarp();   // P reads done before next tile overwrites
    }

    // ---- epilogue: normalize, write g_att[B,S,E] ----
    float inv0 = 1.0f / l0r;
    float inv1 = 1.0f / l1r;
    size_t row0 = (size_t)(b * SEQ + q0 + wrow + g);
    size_t row1 = row0 + 8;
#pragma unroll
    for (int n = 0; n < 16; n++) {
        int d = n * 8 + 2 * q;
        *(float2*)&g_att[row0 * EMB + h * HDIM + d] =
            make_float2(accO[n][0] * inv0, accO[n][1] * inv0);
        *(float2*)&g_att[row1 * EMB + h * HDIM + d] =
            make_float2(accO[n][2] * inv1, accO[n][3] * inv1);
    }
}

// =====================================================================
// launch
// =====================================================================
extern "C" void kernel_launch(void* const* d_in, const int* in_sizes, int n_in,
                              void* d_out, int out_size)
{
    (void)in_sizes; (void)n_in; (void)out_size;
    const float* x     = (const float*)d_in[0];   // [B,S,E]
    const float* Wqkv  = (const float*)d_in[1];   // [3E,E]
    const float* Wproj = (const float*)d_in[2];   // [E,E]
    float* out = (float*)d_out;                   // [B,S,E]

    // 1) qkv = x @ Wqkv^T, scattered into g_q/g_k/g_v [B,H,S,D]
    dim3 g1(EMB3 / GBN, MROWS / GBM);
    sgemm_tf32_kernel<0><<<g1, 256>>>(x, Wqkv, nullptr, MROWS, EMB3, EMB);

    // 2) causal flash attention (tf32 tensor cores) -> g_att [B,S,E]
    cudaFuncSetAttribute(attn_tf32_kernel,
                         cudaFuncAttributeMaxDynamicSharedMemorySize,
                         ATTN_SMEM_BYTES);
    dim3 g2(SEQ / AT_BR, HEADS, BATCH);
    attn_tf32_kernel<<<g2, 128, ATTN_SMEM_BYTES>>>();

    // 3) out = g_att @ Wproj^T
    dim3 g3(EMB / GBN, MROWS / GBM);
    sgemm_tf32_kernel<1><<<g3, 256>>>(nullptr, Wproj, out, MROWS, EMB, EMB);
}

// round 5
// speedup vs baseline: 4.7387x; 1.1128x over previous
#include <cuda_runtime.h>
#include <cstdint>

// Problem constants (fixed shapes from reference)
#define HEADS   16
#define HDIM    128
#define EMB     2048
#define EMB3    6144
#define SEQ     2048
#define BATCH   2
#define MROWS   (BATCH*SEQ)        // 4096

// Scratch (allocation-free rule: __device__ globals)
__device__ float g_q[(size_t)BATCH*HEADS*SEQ*HDIM];
__device__ float g_k[(size_t)BATCH*HEADS*SEQ*HDIM];
__device__ float g_v[(size_t)BATCH*HEADS*SEQ*HDIM];
__device__ float g_att[(size_t)MROWS*EMB];

// ---------- helpers ----------
__device__ __forceinline__ uint32_t smem_u32(const void* p) {
    uint32_t a;
    asm("{ .reg .u64 t; cvta.to.shared.u64 t, %1; cvt.u32.u64 %0, t; }"
        : "=r"(a) : "l"(p));
    return a;
}
__device__ __forceinline__ uint32_t f2tf32(float f) {
    uint32_t r;
    asm("cvt.rna.tf32.f32 %0, %1;" : "=r"(r) : "f"(f));
    return r;
}
__device__ __forceinline__ void mma_tf32(float* c, const uint32_t* a,
                                         uint32_t b0, uint32_t b1) {
    asm volatile(
        "mma.sync.aligned.m16n8k8.row.col.f32.tf32.tf32.f32 "
        "{%0,%1,%2,%3}, {%4,%5,%6,%7}, {%8,%9}, {%0,%1,%2,%3};"
        : "+f"(c[0]), "+f"(c[1]), "+f"(c[2]), "+f"(c[3])
        : "r"(a[0]), "r"(a[1]), "r"(a[2]), "r"(a[3]), "r"(b0), "r"(b1));
}
#define CP_ASYNC16(dst, src) \
    asm volatile("cp.async.cg.shared.global [%0], [%1], 16;" \
                 :: "r"(dst), "l"(src))
#define CP_COMMIT()  asm volatile("cp.async.commit_group;" ::: "memory")
#define CP_WAIT0()   asm volatile("cp.async.wait_group 0;" ::: "memory")

// =====================================================================
// TF32 tensor-core GEMM v2: C[M,N] = A[M,K] * B[N,K]^T (row-major, K contig)
// 128x128x32 block, 256 threads (8 warps @ 64x32 warp tile, 4x4 frags of
// m16n8k8). cp.async fp32 staging into double-buffered smem (xor-swizzled
// 128B rows); cvt.rna.tf32 at fragment-load time. One barrier per K-chunk.
// __launch_bounds__(256,2) -> 2 blocks/SM.
// MODE 0: epilogue scatters into g_q/g_k/g_v as [B,H,S,D]
// MODE 1: A is g_att (internal), epilogue writes C directly
// =====================================================================
#define GBM 128
#define GBN 128
#define GBK 32
#define TILE_W    (GBM * GBK)            // floats per tile (4096)
#define GEMM_SMEM_BYTES (2 * 2 * TILE_W * 4)   // 2 bufs x (A+B) = 65536

template<int MODE>
__global__ void __launch_bounds__(256, 2) sgemm_tf32_v2(
    const float* __restrict__ A, const float* __restrict__ Bw,
    float* __restrict__ C, int M, int N, int K)
{
    extern __shared__ float sm[];
    // layout: buf b: A at sm + b*2*TILE_W, B at sm + b*2*TILE_W + TILE_W
    const uint32_t sbase = smem_u32(sm);

    const float* Ap = (MODE == 1) ? (const float*)g_att : A;

    const int tid  = threadIdx.x;
    const int warp = tid >> 5;
    const int lane = tid & 31;
    const int g    = lane >> 2;   // fragment group (0..7)
    const int q    = lane & 3;    // fragment quad-thread (0..3)

    const int bm = blockIdx.y * GBM;
    const int bn = blockIdx.x * GBN;
    const int wm = (warp >> 2) * 64;   // warp m-offset (0 or 64)
    const int wn = (warp & 3) * 32;    // warp n-offset (0,32,64,96)

    // staging ids: rows r = p*32 + srow (p=0..3), 16B chunk scc (0..7)
    const int srow = tid >> 3;          // 0..31
    const int scc  = tid & 7;           // 0..7
    // swizzled float offsets within a tile
    uint32_t soff[4];
#pragma unroll
    for (int p = 0; p < 4; p++) {
        int r = p * 32 + srow;
        soff[p] = (uint32_t)r * GBK + (uint32_t)((scc ^ (r & 7)) * 4);
    }

    float acc[4][4][4];
#pragma unroll
    for (int i = 0; i < 4; i++)
#pragma unroll
        for (int j = 0; j < 4; j++)
#pragma unroll
            for (int e = 0; e < 4; e++) acc[i][j][e] = 0.f;

    const int NIT = K / GBK;

    // prologue: stage chunk 0 into buffer 0
    {
        const uint32_t dA = sbase;
        const uint32_t dB = sbase + TILE_W * 4;
#pragma unroll
        for (int p = 0; p < 4; p++) {
            const float* as = Ap + (size_t)(bm + p * 32 + srow) * K + scc * 4;
            const float* bs = Bw + (size_t)(bn + p * 32 + srow) * K + scc * 4;
            CP_ASYNC16(dA + soff[p] * 4, as);
            CP_ASYNC16(dB + soff[p] * 4, bs);
        }
        CP_COMMIT();
    }

    for (int it = 0; it < NIT; it++) {
        CP_WAIT0();
        __syncthreads();   // chunk `it` visible to all; compute(it-1) done by all

        // issue chunk it+1 into the other buffer (overlaps compute below)
        if (it + 1 < NIT) {
            const int b1 = (it + 1) & 1;
            const uint32_t dA = sbase + (uint32_t)(b1 * 2 * TILE_W) * 4;
            const uint32_t dB = dA + TILE_W * 4;
            const int k0 = (it + 1) * GBK;
#pragma unroll
            for (int p = 0; p < 4; p++) {
                const float* as = Ap + (size_t)(bm + p * 32 + srow) * K + k0 + scc * 4;
                const float* bs = Bw + (size_t)(bn + p * 32 + srow) * K + k0 + scc * 4;
                CP_ASYNC16(dA + soff[p] * 4, as);
                CP_ASYNC16(dB + soff[p] * 4, bs);
            }
            CP_COMMIT();
        }

        // compute chunk it
        const float* As = sm + (it & 1) * 2 * TILE_W;
        const float* Bs = As + TILE_W;
#pragma unroll
        for (int ks = 0; ks < 4; ks++) {
            const int qa0 = ((2 * ks)     ^ g) * 4 + q;  // col for a0/a1/b0
            const int qa1 = ((2 * ks + 1) ^ g) * 4 + q;  // col for a2/a3/b1
            uint32_t a[4][4];
#pragma unroll
            for (int i = 0; i < 4; i++) {
                const int m0 = wm + i * 16 + g;
                a[i][0] = f2tf32(As[m0 * GBK + qa0]);
                a[i][1] = f2tf32(As[(m0 + 8) * GBK + qa0]);
                a[i][2] = f2tf32(As[m0 * GBK + qa1]);
                a[i][3] = f2tf32(As[(m0 + 8) * GBK + qa1]);
            }
#pragma unroll
            for (int j = 0; j < 4; j++) {
                const int n0 = wn + j * 8 + g;
                const uint32_t b0 = f2tf32(Bs[n0 * GBK + qa0]);
                const uint32_t b1 = f2tf32(Bs[n0 * GBK + qa1]);
#pragma unroll
                for (int i = 0; i < 4; i++)
                    mma_tf32(acc[i][j], a[i], b0, b1);
            }
        }
    }

    // epilogue: fragment (i,j): rows bm+wm+i*16+{g, g+8}, cols bn+wn+j*8+{2q,2q+1}
#pragma unroll
    for (int i = 0; i < 4; i++) {
#pragma unroll
        for (int j = 0; j < 4; j++) {
            int r0 = bm + wm + i * 16 + g;
            int n0 = bn + wn + j * 8 + 2 * q;
            if (MODE == 0) {
                int which = n0 >> 11;
                int hh    = (n0 >> 7) & (HEADS - 1);
                int d     = n0 & (HDIM - 1);
                int b     = r0 >> 11;
                float* base = (which == 0 ? g_q : which == 1 ? g_k : g_v)
                              + ((size_t)(b * HEADS + hh)) * SEQ * HDIM;
                int s0 = r0 & (SEQ - 1);
                *(float2*)&base[(size_t)s0 * HDIM + d] =
                    make_float2(acc[i][j][0], acc[i][j][1]);
                *(float2*)&base[(size_t)(s0 + 8) * HDIM + d] =
                    make_float2(acc[i][j][2], acc[i][j][3]);
            } else {
                *(float2*)(C + (size_t)r0 * N + n0) =
                    make_float2(acc[i][j][0], acc[i][j][1]);
                *(float2*)(C + (size_t)(r0 + 8) * N + n0) =
                    make_float2(acc[i][j][2], acc[i][j][3]);
            }
        }
    }
}

// =====================================================================
// TF32 tensor-core flash attention (causal). Unchanged from R3.
// Block = (64 q-rows, head, batch), 128 threads = 4 warps x 16-row tiles.
// =====================================================================
#define AT_BR 64
#define AT_BC 64
#define KST   132
#define PST   68
#define ATTN_SMEM_WORDS (2 * AT_BC * KST + AT_BR * PST)
#define ATTN_SMEM_BYTES (ATTN_SMEM_WORDS * 4)

__global__ void __launch_bounds__(128) attn_tf32_kernel()
{
    extern __shared__ uint32_t smw[];
    uint32_t* Ks = smw;
    uint32_t* Vs = Ks + AT_BC * KST;
    uint32_t* Ps = Vs + AT_BC * KST;

    const int t    = threadIdx.x;
    const int warp = t >> 5;
    const int lane = t & 31;
    const int g    = lane >> 2;
    const int q    = lane & 3;
    const int wrow = warp * 16;

    const int qt = blockIdx.x, h = blockIdx.y, b = blockIdx.z;
    const int q0 = qt * AT_BR;
    const size_t headBase = ((size_t)(b * HEADS + h)) * SEQ * HDIM;
    const float scale = 0.08838834764831845f;   // 1/sqrt(128)

    {
        const float4* Qg = (const float4*)(g_q + headBase + (size_t)q0 * HDIM);
#pragma unroll
        for (int i = 0; i < 16; i++) {
            int idx = t + i * 128;
            int row = idx >> 5, c = idx & 31;
            float4 v = Qg[idx];
            uint4 u = make_uint4(f2tf32(v.x * scale), f2tf32(v.y * scale),
                                 f2tf32(v.z * scale), f2tf32(v.w * scale));
            *(uint4*)&Ks[row * KST + c * 4] = u;
        }
    }
    __syncthreads();

    uint32_t qf[16][4];
#pragma unroll
    for (int ks = 0; ks < 16; ks++) {
        qf[ks][0] = Ks[(wrow + g)     * KST + ks * 8 + q];
        qf[ks][1] = Ks[(wrow + g + 8) * KST + ks * 8 + q];
        qf[ks][2] = Ks[(wrow + g)     * KST + ks * 8 + q + 4];
        qf[ks][3] = Ks[(wrow + g + 8) * KST + ks * 8 + q + 4];
    }

    float accO[16][4];
#pragma unroll
    for (int n = 0; n < 16; n++)
#pragma unroll
        for (int e = 0; e < 4; e++) accO[n][e] = 0.f;

    float m0r = -1e30f, m1r = -1e30f;
    float l0r = 0.f, l1r = 0.f;

    for (int kt = 0; kt <= qt; kt++) {
        __syncthreads();
        {
            const float4* Kg = (const float4*)(g_k + headBase + (size_t)(kt * AT_BC) * HDIM);
            const float4* Vg = (const float4*)(g_v + headBase + (size_t)(kt * AT_BC) * HDIM);
#pragma unroll
            for (int i = 0; i < 16; i++) {
                int idx = t + i * 128;
                int row = idx >> 5, c = idx & 31;
                float4 kv = Kg[idx];
                float4 vv = Vg[idx];
                *(uint4*)&Ks[row * KST + c * 4] =
                    make_uint4(f2tf32(kv.x), f2tf32(kv.y), f2tf32(kv.z), f2tf32(kv.w));
                *(uint4*)&Vs[row * KST + c * 4] =
                    make_uint4(f2tf32(vv.x), f2tf32(vv.y), f2tf32(vv.z), f2tf32(vv.w));
            }
        }
        __syncthreads();

        float sc[8][4];
#pragma unroll
        for (int n = 0; n < 8; n++)
#pragma unroll
            for (int e = 0; e < 4; e++) sc[n][e] = 0.f;

#pragma unroll
        for (int ks = 0; ks < 16; ks++) {
#pragma unroll
            for (int n = 0; n < 8; n++) {
                uint32_t b0 = Ks[(n * 8 + g) * KST + ks * 8 + q];
                uint32_t b1 = Ks[(n * 8 + g) * KST + ks * 8 + q + 4];
                mma_tf32(sc[n], qf[ks], b0, b1);
            }
        }

        if (kt == qt) {
            int r0 = wrow + g, r1 = wrow + g + 8;
#pragma unroll
            for (int n = 0; n < 8; n++) {
                int c0 = n * 8 + 2 * q, c1 = c0 + 1;
                if (c0 > r0) sc[n][0] = -1e30f;
                if (c1 > r0) sc[n][1] = -1e30f;
                if (c0 > r1) sc[n][2] = -1e30f;
                if (c1 > r1) sc[n][3] = -1e30f;
            }
        }

        float pm0 = -1e30f, pm1 = -1e30f;
#pragma unroll
        for (int n = 0; n < 8; n++) {
            pm0 = fmaxf(pm0, fmaxf(sc[n][0], sc[n][1]));
            pm1 = fmaxf(pm1, fmaxf(sc[n][2], sc[n][3]));
        }
        pm0 = fmaxf(pm0, __shfl_xor_sync(0xffffffffu, pm0, 1));
        pm0 = fmaxf(pm0, __shfl_xor_sync(0xffffffffu, pm0, 2));
        pm1 = fmaxf(pm1, __shfl_xor_sync(0xffffffffu, pm1, 1));
        pm1 = fmaxf(pm1, __shfl_xor_sync(0xffffffffu, pm1, 2));

        float mn0 = fmaxf(m0r, pm0);
        float mn1 = fmaxf(m1r, pm1);
        float al0 = __expf(m0r - mn0);
        float al1 = __expf(m1r - mn1);
        m0r = mn0; m1r = mn1;

        float ps0 = 0.f, ps1 = 0.f;
#pragma unroll
        for (int n = 0; n < 8; n++) {
            float p00 = __expf(sc[n][0] - mn0);
            float p01 = __expf(sc[n][1] - mn0);
            float p10 = __expf(sc[n][2] - mn1);
            float p11 = __expf(sc[n][3] - mn1);
            ps0 += p00 + p01;
            ps1 += p10 + p11;
            uint32_t* pr0 = &Ps[(wrow + g) * PST + n * 8 + 2 * q];
            uint32_t* pr1 = &Ps[(wrow + g + 8) * PST + n * 8 + 2 * q];
            pr0[0] = f2tf32(p00); pr0[1] = f2tf32(p01);
            pr1[0] = f2tf32(p10); pr1[1] = f2tf32(p11);
        }
        ps0 += __shfl_xor_sync(0xffffffffu, ps0, 1);
        ps0 += __shfl_xor_sync(0xffffffffu, ps0, 2);
        ps1 += __shfl_xor_sync(0xffffffffu, ps1, 1);
        ps1 += __shfl_xor_sync(0xffffffffu, ps1, 2);
        l0r = l0r * al0 + ps0;
        l1r = l1r * al1 + ps1;

#pragma unroll
        for (int n = 0; n < 16; n++) {
            accO[n][0] *= al0; accO[n][1] *= al0;
            accO[n][2] *= al1; accO[n][3] *= al1;
        }

        __syncwarp();

#pragma unroll
        for (int ks = 0; ks < 8; ks++) {
            uint32_t pa[4];
            pa[0] = Ps[(wrow + g)     * PST + ks * 8 + q];
            pa[1] = Ps[(wrow + g + 8) * PST + ks * 8 + q];
            pa[2] = Ps[(wrow + g)     * PST + ks * 8 + q + 4];
            pa[3] = Ps[(wrow + g + 8) * PST + ks * 8 + q + 4];
#pragma unroll
            for (int n = 0; n < 16; n++) {
                uint32_t b0 = Vs[(ks * 8 + q)     * KST + n * 8 + g];
                uint32_t b1 = Vs[(ks * 8 + q + 4) * KST + n * 8 + g];
                mma_tf32(accO[n], pa, b0, b1);
            }
        }
        __syncwarp();
    }

    float inv0 = 1.0f / l0r;
    float inv1 = 1.0f / l1r;
    size_t row0 = (size_t)(b * SEQ + q0 + wrow + g);
    size_t row1 = row0 + 8;
#pragma unroll
    for (int n = 0; n < 16; n++) {
        int d = n * 8 + 2 * q;
        *(float2*)&g_att[row0 * EMB + h * HDIM + d] =
            make_float2(accO[n][0] * inv0, accO[n][1] * inv0);
        *(float2*)&g_att[row1 * EMB + h * HDIM + d] =
            make_float2(accO[n][2] * inv1, accO[n][3] * inv1);
    }
}

// =====================================================================
// launch
// =====================================================================
extern "C" void kernel_launch(void* const* d_in, const int* in_sizes, int n_in,
                              void* d_out, int out_size)
{
    (void)in_sizes; (void)n_in; (void)out_size;
    const float* x     = (const float*)d_in[0];   // [B,S,E]
    const float* Wqkv  = (const float*)d_in[1];   // [3E,E]
    const float* Wproj = (const float*)d_in[2];   // [E,E]
    float* out = (float*)d_out;                   // [B,S,E]

    cudaFuncSetAttribute(sgemm_tf32_v2<0>,
                         cudaFuncAttributeMaxDynamicSharedMemorySize,
                         GEMM_SMEM_BYTES);
    cudaFuncSetAttribute(sgemm_tf32_v2<1>,
                         cudaFuncAttributeMaxDynamicSharedMemorySize,
                         GEMM_SMEM_BYTES);
    cudaFuncSetAttribute(attn_tf32_kernel,
                         cudaFuncAttributeMaxDynamicSharedMemorySize,
                         ATTN_SMEM_BYTES);

    // 1) qkv = x @ Wqkv^T, scattered into g_q/g_k/g_v [B,H,S,D]
    dim3 g1(EMB3 / GBN, MROWS / GBM);
    sgemm_tf32_v2<0><<<g1, 256, GEMM_SMEM_BYTES>>>(x, Wqkv, nullptr, MROWS, EMB3, EMB);

    // 2) causal flash attention (tf32 tensor cores) -> g_att [B,S,E]
    dim3 g2(SEQ / AT_BR, HEADS, BATCH);
    attn_tf32_kernel<<<g2, 128, ATTN_SMEM_BYTES>>>();

    // 3) out = g_att @ Wproj^T
    dim3 g3(EMB / GBN, MROWS / GBM);
    sgemm_tf32_v2<1><<<g3, 256, GEMM_SMEM_BYTES>>>(nullptr, Wproj, out, MROWS, EMB, EMB);
}

// round 6
// speedup vs baseline: 5.1492x; 1.0866x over previous
#include <cuda_runtime.h>
#include <cstdint>

// Problem constants (fixed shapes from reference)
#define HEADS   16
#define HDIM    128
#define EMB     2048
#define EMB3    6144
#define SEQ     2048
#define BATCH   2
#define MROWS   (BATCH*SEQ)        // 4096

// Scratch (allocation-free rule: __device__ globals).
// All inter-kernel tensors carry tf32 bit patterns in uint32.
__device__ uint32_t g_q[(size_t)BATCH*HEADS*SEQ*HDIM];
__device__ uint32_t g_k[(size_t)BATCH*HEADS*SEQ*HDIM];
__device__ uint32_t g_v[(size_t)BATCH*HEADS*SEQ*HDIM];
__device__ uint32_t g_att[(size_t)MROWS*EMB];
__device__ uint32_t g_xt[(size_t)MROWS*EMB];
__device__ uint32_t g_wqt[(size_t)EMB3*EMB];
__device__ uint32_t g_wpt[(size_t)EMB*EMB];

// ---------- helpers ----------
__device__ __forceinline__ uint32_t smem_u32(const void* p) {
    uint32_t a;
    asm("{ .reg .u64 t; cvta.to.shared.u64 t, %1; cvt.u32.u64 %0, t; }"
        : "=r"(a) : "l"(p));
    return a;
}
__device__ __forceinline__ uint32_t f2tf32(float f) {
    uint32_t r;
    asm("cvt.rna.tf32.f32 %0, %1;" : "=r"(r) : "f"(f));
    return r;
}
__device__ __forceinline__ void mma_tf32(float* c, const uint32_t* a,
                                         uint32_t b0, uint32_t b1) {
    asm volatile(
        "mma.sync.aligned.m16n8k8.row.col.f32.tf32.tf32.f32 "
        "{%0,%1,%2,%3}, {%4,%5,%6,%7}, {%8,%9}, {%0,%1,%2,%3};"
        : "+f"(c[0]), "+f"(c[1]), "+f"(c[2]), "+f"(c[3])
        : "r"(a[0]), "r"(a[1]), "r"(a[2]), "r"(a[3]), "r"(b0), "r"(b1));
}
#define CP_ASYNC16(dst, src) \
    asm volatile("cp.async.cg.shared.global [%0], [%1], 16;" \
                 :: "r"(dst), "l"(src))
#define CP_COMMIT()  asm volatile("cp.async.commit_group;" ::: "memory")
#define CP_WAIT0()   asm volatile("cp.async.wait_group 0;" ::: "memory")

// ---------- prepass: fp32 -> tf32 bits ----------
template<int W>
__global__ void __launch_bounds__(256) cvt_tf32_kernel(const float* __restrict__ src, int n)
{
    uint32_t* dst = (W == 0) ? g_xt : (W == 1) ? g_wqt : g_wpt;
    int i = blockIdx.x * blockDim.x + threadIdx.x;
    int stride = gridDim.x * blockDim.x;
    int n4 = n >> 2;
    for (; i < n4; i += stride) {
        float4 v = ((const float4*)src)[i];
        ((uint4*)dst)[i] = make_uint4(f2tf32(v.x), f2tf32(v.y),
                                      f2tf32(v.z), f2tf32(v.w));
    }
}

// =====================================================================
// TF32 tensor-core GEMM v3: C[M,N] = A[M,K] * B[N,K]^T.
// Operands are pre-converted tf32 bits (uint32). Inner loop is pure
// LDS + MMA. 128x128x32 block, 256 threads, 8 warps @ 64x32,
// double-buffered cp.async smem, one barrier per K-chunk, 2 blocks/SM.
// MODE 0: A=g_xt, B=g_wqt; epilogue scatters tf32 bits into g_q/g_k/g_v
// MODE 1: A=g_att, B=g_wpt; epilogue writes fp32 C
// =====================================================================
#define GBM 128
#define GBN 128
#define GBK 32
#define TILE_W    (GBM * GBK)            // words per tile (4096)
#define GEMM_SMEM_BYTES (2 * 2 * TILE_W * 4)   // 65536

template<int MODE>
__global__ void __launch_bounds__(256, 2) sgemm_tf32_v3(
    float* __restrict__ C, int M, int N, int K)
{
    extern __shared__ uint32_t sm[];
    const uint32_t sbase = smem_u32(sm);

    const uint32_t* Ap = (MODE == 1) ? g_att : g_xt;
    const uint32_t* Bw = (MODE == 1) ? g_wpt : g_wqt;

    const int tid  = threadIdx.x;
    const int warp = tid >> 5;
    const int lane = tid & 31;
    const int g    = lane >> 2;   // fragment group (0..7)
    const int q    = lane & 3;    // fragment quad-thread (0..3)

    const int bm = blockIdx.y * GBM;
    const int bn = blockIdx.x * GBN;
    const int wm = (warp >> 2) * 64;   // warp m-offset (0 or 64)
    const int wn = (warp & 3) * 32;    // warp n-offset (0,32,64,96)

    // staging ids: rows r = p*32 + srow (p=0..3), 16B chunk scc (0..7)
    const int srow = tid >> 3;          // 0..31
    const int scc  = tid & 7;           // 0..7
    uint32_t soff[4];
#pragma unroll
    for (int p = 0; p < 4; p++) {
        int r = p * 32 + srow;
        soff[p] = (uint32_t)r * GBK + (uint32_t)((scc ^ (r & 7)) * 4);
    }

    float acc[4][4][4];
#pragma unroll
    for (int i = 0; i < 4; i++)
#pragma unroll
        for (int j = 0; j < 4; j++)
#pragma unroll
            for (int e = 0; e < 4; e++) acc[i][j][e] = 0.f;

    const int NIT = K / GBK;

    // prologue: stage chunk 0 into buffer 0
    {
        const uint32_t dA = sbase;
        const uint32_t dB = sbase + TILE_W * 4;
#pragma unroll
        for (int p = 0; p < 4; p++) {
            const uint32_t* as = Ap + (size_t)(bm + p * 32 + srow) * K + scc * 4;
            const uint32_t* bs = Bw + (size_t)(bn + p * 32 + srow) * K + scc * 4;
            CP_ASYNC16(dA + soff[p] * 4, as);
            CP_ASYNC16(dB + soff[p] * 4, bs);
        }
        CP_COMMIT();
    }

    for (int it = 0; it < NIT; it++) {
        CP_WAIT0();
        __syncthreads();

        if (it + 1 < NIT) {
            const int b1 = (it + 1) & 1;
            const uint32_t dA = sbase + (uint32_t)(b1 * 2 * TILE_W) * 4;
            const uint32_t dB = dA + TILE_W * 4;
            const int k0 = (it + 1) * GBK;
#pragma unroll
            for (int p = 0; p < 4; p++) {
                const uint32_t* as = Ap + (size_t)(bm + p * 32 + srow) * K + k0 + scc * 4;
                const uint32_t* bs = Bw + (size_t)(bn + p * 32 + srow) * K + k0 + scc * 4;
                CP_ASYNC16(dA + soff[p] * 4, as);
                CP_ASYNC16(dB + soff[p] * 4, bs);
            }
            CP_COMMIT();
        }

        const uint32_t* As = sm + (it & 1) * 2 * TILE_W;
        const uint32_t* Bs = As + TILE_W;
#pragma unroll
        for (int ks = 0; ks < 4; ks++) {
            const int qa0 = ((2 * ks)     ^ g) * 4 + q;
            const int qa1 = ((2 * ks + 1) ^ g) * 4 + q;
            uint32_t a[4][4];
#pragma unroll
            for (int i = 0; i < 4; i++) {
                const int m0 = wm + i * 16 + g;
                a[i][0] = As[m0 * GBK + qa0];
                a[i][1] = As[(m0 + 8) * GBK + qa0];
                a[i][2] = As[m0 * GBK + qa1];
                a[i][3] = As[(m0 + 8) * GBK + qa1];
            }
#pragma unroll
            for (int j = 0; j < 4; j++) {
                const int n0 = wn + j * 8 + g;
                const uint32_t b0 = Bs[n0 * GBK + qa0];
                const uint32_t b1 = Bs[n0 * GBK + qa1];
#pragma unroll
                for (int i = 0; i < 4; i++)
                    mma_tf32(acc[i][j], a[i], b0, b1);
            }
        }
    }

    // epilogue
#pragma unroll
    for (int i = 0; i < 4; i++) {
#pragma unroll
        for (int j = 0; j < 4; j++) {
            int r0 = bm + wm + i * 16 + g;
            int n0 = bn + wn + j * 8 + 2 * q;
            if (MODE == 0) {
                int which = n0 >> 11;
                int hh    = (n0 >> 7) & (HEADS - 1);
                int d     = n0 & (HDIM - 1);
                int b     = r0 >> 11;
                uint32_t* base = (which == 0 ? g_q : which == 1 ? g_k : g_v)
                                 + ((size_t)(b * HEADS + hh)) * SEQ * HDIM;
                int s0 = r0 & (SEQ - 1);
                *(uint2*)&base[(size_t)s0 * HDIM + d] =
                    make_uint2(f2tf32(acc[i][j][0]), f2tf32(acc[i][j][1]));
                *(uint2*)&base[(size_t)(s0 + 8) * HDIM + d] =
                    make_uint2(f2tf32(acc[i][j][2]), f2tf32(acc[i][j][3]));
            } else {
                *(float2*)(C + (size_t)r0 * N + n0) =
                    make_float2(acc[i][j][0], acc[i][j][1]);
                *(float2*)(C + (size_t)(r0 + 8) * N + n0) =
                    make_float2(acc[i][j][2], acc[i][j][3]);
            }
        }
    }
}

// =====================================================================
// TF32 tensor-core flash attention (causal). All operands arrive as tf32
// bits; staging is a raw copy. Score scale applied post-MMA.
// Block = (64 q-rows, head, batch), 128 threads = 4 warps x 16-row tiles.
// =====================================================================
#define AT_BR 64
#define AT_BC 64
#define KST   132
#define PST   68
#define ATTN_SMEM_WORDS (2 * AT_BC * KST + AT_BR * PST)
#define ATTN_SMEM_BYTES (ATTN_SMEM_WORDS * 4)

__global__ void __launch_bounds__(128) attn_tf32_kernel()
{
    extern __shared__ uint32_t smw[];
    uint32_t* Ks = smw;
    uint32_t* Vs = Ks + AT_BC * KST;
    uint32_t* Ps = Vs + AT_BC * KST;

    const int t    = threadIdx.x;
    const int warp = t >> 5;
    const int lane = t & 31;
    const int g    = lane >> 2;
    const int q    = lane & 3;
    const int wrow = warp * 16;

    const int qt = blockIdx.x, h = blockIdx.y, b = blockIdx.z;
    const int q0 = qt * AT_BR;
    const size_t headBase = ((size_t)(b * HEADS + h)) * SEQ * HDIM;
    const float scale = 0.08838834764831845f;   // 1/sqrt(128)

    // stage Q tile (raw tf32 bits copy)
    {
        const uint4* Qg = (const uint4*)(g_q + headBase + (size_t)q0 * HDIM);
#pragma unroll
        for (int i = 0; i < 16; i++) {
            int idx = t + i * 128;
            int row = idx >> 5, c = idx & 31;
            *(uint4*)&Ks[row * KST + c * 4] = Qg[idx];
        }
    }
    __syncthreads();

    uint32_t qf[16][4];
#pragma unroll
    for (int ks = 0; ks < 16; ks++) {
        qf[ks][0] = Ks[(wrow + g)     * KST + ks * 8 + q];
        qf[ks][1] = Ks[(wrow + g + 8) * KST + ks * 8 + q];
        qf[ks][2] = Ks[(wrow + g)     * KST + ks * 8 + q + 4];
        qf[ks][3] = Ks[(wrow + g + 8) * KST + ks * 8 + q + 4];
    }

    float accO[16][4];
#pragma unroll
    for (int n = 0; n < 16; n++)
#pragma unroll
        for (int e = 0; e < 4; e++) accO[n][e] = 0.f;

    float m0r = -1e30f, m1r = -1e30f;
    float l0r = 0.f, l1r = 0.f;

    for (int kt = 0; kt <= qt; kt++) {
        __syncthreads();
        {
            const uint4* Kg = (const uint4*)(g_k + headBase + (size_t)(kt * AT_BC) * HDIM);
            const uint4* Vg = (const uint4*)(g_v + headBase + (size_t)(kt * AT_BC) * HDIM);
#pragma unroll
            for (int i = 0; i < 16; i++) {
                int idx = t + i * 128;
                int row = idx >> 5, c = idx & 31;
                *(uint4*)&Ks[row * KST + c * 4] = Kg[idx];
                *(uint4*)&Vs[row * KST + c * 4] = Vg[idx];
            }
        }
        __syncthreads();

        float sc[8][4];
#pragma unroll
        for (int n = 0; n < 8; n++)
#pragma unroll
            for (int e = 0; e < 4; e++) sc[n][e] = 0.f;

#pragma unroll
        for (int ks = 0; ks < 16; ks++) {
#pragma unroll
            for (int n = 0; n < 8; n++) {
                uint32_t b0 = Ks[(n * 8 + g) * KST + ks * 8 + q];
                uint32_t b1 = Ks[(n * 8 + g) * KST + ks * 8 + q + 4];
                mma_tf32(sc[n], qf[ks], b0, b1);
            }
        }

        // apply 1/sqrt(D) scale post-MMA
#pragma unroll
        for (int n = 0; n < 8; n++)
#pragma unroll
            for (int e = 0; e < 4; e++) sc[n][e] *= scale;

        if (kt == qt) {
            int r0 = wrow + g, r1 = wrow + g + 8;
#pragma unroll
            for (int n = 0; n < 8; n++) {
                int c0 = n * 8 + 2 * q, c1 = c0 + 1;
                if (c0 > r0) sc[n][0] = -1e30f;
                if (c1 > r0) sc[n][1] = -1e30f;
                if (c0 > r1) sc[n][2] = -1e30f;
                if (c1 > r1) sc[n][3] = -1e30f;
            }
        }

        float pm0 = -1e30f, pm1 = -1e30f;
#pragma unroll
        for (int n = 0; n < 8; n++) {
            pm0 = fmaxf(pm0, fmaxf(sc[n][0], sc[n][1]));
            pm1 = fmaxf(pm1, fmaxf(sc[n][2], sc[n][3]));
        }
        pm0 = fmaxf(pm0, __shfl_xor_sync(0xffffffffu, pm0, 1));
        pm0 = fmaxf(pm0, __shfl_xor_sync(0xffffffffu, pm0, 2));
        pm1 = fmaxf(pm1, __shfl_xor_sync(0xffffffffu, pm1, 1));
        pm1 = fmaxf(pm1, __shfl_xor_sync(0xffffffffu, pm1, 2));

        float mn0 = fmaxf(m0r, pm0);
        float mn1 = fmaxf(m1r, pm1);
        float al0 = __expf(m0r - mn0);
        float al1 = __expf(m1r - mn1);
        m0r = mn0; m1r = mn1;

        float ps0 = 0.f, ps1 = 0.f;
#pragma unroll
        for (int n = 0; n < 8; n++) {
            float p00 = __expf(sc[n][0] - mn0);
            float p01 = __expf(sc[n][1] - mn0);
            float p10 = __expf(sc[n][2] - mn1);
            float p11 = __expf(sc[n][3] - mn1);
            ps0 += p00 + p01;
            ps1 += p10 + p11;
            uint32_t* pr0 = &Ps[(wrow + g) * PST + n * 8 + 2 * q];
            uint32_t* pr1 = &Ps[(wrow + g + 8) * PST + n * 8 + 2 * q];
            pr0[0] = f2tf32(p00); pr0[1] = f2tf32(p01);
            pr1[0] = f2tf32(p10); pr1[1] = f2tf32(p11);
        }
        ps0 += __shfl_xor_sync(0xffffffffu, ps0, 1);
        ps0 += __shfl_xor_sync(0xffffffffu, ps0, 2);
        ps1 += __shfl_xor_sync(0xffffffffu, ps1, 1);
        ps1 += __shfl_xor_sync(0xffffffffu, ps1, 2);
        l0r = l0r * al0 + ps0;
        l1r = l1r * al1 + ps1;

#pragma unroll
        for (int n = 0; n < 16; n++) {
            accO[n][0] *= al0; accO[n][1] *= al0;
            accO[n][2] *= al1; accO[n][3] *= al1;
        }

        __syncwarp();

#pragma unroll
        for (int ks = 0; ks < 8; ks++) {
            uint32_t pa[4];
            pa[0] = Ps[(wrow + g)     * PST + ks * 8 + q];
            pa[1] = Ps[(wrow + g + 8) * PST + ks * 8 + q];
            pa[2] = Ps[(wrow + g)     * PST + ks * 8 + q + 4];
            pa[3] = Ps[(wrow + g + 8) * PST + ks * 8 + q + 4];
#pragma unroll
            for (int n = 0; n < 16; n++) {
                uint32_t b0 = Vs[(ks * 8 + q)     * KST + n * 8 + g];
                uint32_t b1 = Vs[(ks * 8 + q + 4) * KST + n * 8 + g];
                mma_tf32(accO[n], pa, b0, b1);
            }
        }
        __syncwarp();
    }

    // epilogue: normalize, write tf32 bits to g_att
    float inv0 = 1.0f / l0r;
    float inv1 = 1.0f / l1r;
    size_t row0 = (size_t)(b * SEQ + q0 + wrow + g);
    size_t row1 = row0 + 8;
#pragma unroll
    for (int n = 0; n < 16; n++) {
        int d = n * 8 + 2 * q;
        *(uint2*)&g_att[row0 * EMB + h * HDIM + d] =
            make_uint2(f2tf32(accO[n][0] * inv0), f2tf32(accO[n][1] * inv0));
        *(uint2*)&g_att[row1 * EMB + h * HDIM + d] =
            make_uint2(f2tf32(accO[n][2] * inv1), f2tf32(accO[n][3] * inv1));
    }
}

// =====================================================================
// launch
// =====================================================================
extern "C" void kernel_launch(void* const* d_in, const int* in_sizes, int n_in,
                              void* d_out, int out_size)
{
    (void)in_sizes; (void)n_in; (void)out_size;
    const float* x     = (const float*)d_in[0];   // [B,S,E]
    const float* Wqkv  = (const float*)d_in[1];   // [3E,E]
    const float* Wproj = (const float*)d_in[2];   // [E,E]
    float* out = (float*)d_out;                   // [B,S,E]

    cudaFuncSetAttribute(sgemm_tf32_v3<0>,
                         cudaFuncAttributeMaxDynamicSharedMemorySize,
                         GEMM_SMEM_BYTES);
    cudaFuncSetAttribute(sgemm_tf32_v3<1>,
                         cudaFuncAttributeMaxDynamicSharedMemorySize,
                         GEMM_SMEM_BYTES);
    cudaFuncSetAttribute(attn_tf32_kernel,
                         cudaFuncAttributeMaxDynamicSharedMemorySize,
                         ATTN_SMEM_BYTES);

    // 0) prepass: fp32 -> tf32 bit buffers
    cvt_tf32_kernel<0><<<1024, 256>>>(x,     MROWS * EMB);
    cvt_tf32_kernel<1><<<1024, 256>>>(Wqkv,  EMB3 * EMB);
    cvt_tf32_kernel<2><<<1024, 256>>>(Wproj, EMB * EMB);

    // 1) qkv = x @ Wqkv^T -> g_q/g_k/g_v (tf32 bits, [B,H,S,D])
    dim3 g1(EMB3 / GBN, MROWS / GBM);
    sgemm_tf32_v3<0><<<g1, 256, GEMM_SMEM_BYTES>>>(nullptr, MROWS, EMB3, EMB);

    // 2) causal flash attention -> g_att (tf32 bits, [B,S,E])
    dim3 g2(SEQ / AT_BR, HEADS, BATCH);
    attn_tf32_kernel<<<g2, 128, ATTN_SMEM_BYTES>>>();

    // 3) out = g_att @ Wproj^T (fp32 out)
    dim3 g3(EMB / GBN, MROWS / GBM);
    sgemm_tf32_v3<1><<<g3, 256, GEMM_SMEM_BYTES>>>(out, MROWS, EMB, EMB);
}

// round 7
// speedup vs baseline: 5.2179x; 1.0134x over previous
#include <cuda_runtime.h>
#include <cstdint>

// Problem constants (fixed shapes from reference)
#define HEADS   16
#define HDIM    128
#define EMB     2048
#define EMB3    6144
#define SEQ     2048
#define BATCH   2
#define MROWS   (BATCH*SEQ)        // 4096

// Scratch (allocation-free rule: __device__ globals).
// All inter-kernel tensors carry tf32 bit patterns in uint32.
__device__ uint32_t g_q[(size_t)BATCH*HEADS*SEQ*HDIM];
__device__ uint32_t g_k[(size_t)BATCH*HEADS*SEQ*HDIM];
__device__ uint32_t g_v[(size_t)BATCH*HEADS*SEQ*HDIM];
__device__ uint32_t g_att[(size_t)MROWS*EMB];
__device__ uint32_t g_xt[(size_t)MROWS*EMB];
__device__ uint32_t g_wqt[(size_t)EMB3*EMB];
__device__ uint32_t g_wpt[(size_t)EMB*EMB];

// ---------- helpers ----------
__device__ __forceinline__ uint32_t smem_u32(const void* p) {
    uint32_t a;
    asm("{ .reg .u64 t; cvta.to.shared.u64 t, %1; cvt.u32.u64 %0, t; }"
        : "=r"(a) : "l"(p));
    return a;
}
__device__ __forceinline__ uint32_t f2tf32(float f) {
    uint32_t r;
    asm("cvt.rna.tf32.f32 %0, %1;" : "=r"(r) : "f"(f));
    return r;
}
__device__ __forceinline__ void mma_tf32(float* c, const uint32_t* a,
                                         uint32_t b0, uint32_t b1) {
    asm volatile(
        "mma.sync.aligned.m16n8k8.row.col.f32.tf32.tf32.f32 "
        "{%0,%1,%2,%3}, {%4,%5,%6,%7}, {%8,%9}, {%0,%1,%2,%3};"
        : "+f"(c[0]), "+f"(c[1]), "+f"(c[2]), "+f"(c[3])
        : "r"(a[0]), "r"(a[1]), "r"(a[2]), "r"(a[3]), "r"(b0), "r"(b1));
}
#define CP_ASYNC16(dst, src) \
    asm volatile("cp.async.cg.shared.global [%0], [%1], 16;" \
                 :: "r"(dst), "l"(src))
#define CP_COMMIT()  asm volatile("cp.async.commit_group;" ::: "memory")
#define CP_WAIT1()   asm volatile("cp.async.wait_group 1;" ::: "memory")

// ---------- prepass: fp32 -> tf32 bits ----------
template<int W>
__global__ void __launch_bounds__(256) cvt_tf32_kernel(const float* __restrict__ src, int n)
{
    uint32_t* dst = (W == 0) ? g_xt : (W == 1) ? g_wqt : g_wpt;
    int i = blockIdx.x * blockDim.x + threadIdx.x;
    int stride = gridDim.x * blockDim.x;
    int n4 = n >> 2;
    for (; i < n4; i += stride) {
        float4 v = ((const float4*)src)[i];
        ((uint4*)dst)[i] = make_uint4(f2tf32(v.x), f2tf32(v.y),
                                      f2tf32(v.z), f2tf32(v.w));
    }
}

// =====================================================================
// TF32 tensor-core GEMM v4: C[M,N] = A[M,K] * B[N,K]^T.
// Pre-converted tf32 operands; pure LDS+MMA inner loop.
// 128x128x32 block, 256 threads, 8 warps @ 64x32 warp tiles.
// 3-stage cp.async pipeline, wait_group 1 (2 chunks of latency budget),
// one barrier per K-chunk, 2 blocks/SM.
// MODE 0: A=g_xt, B=g_wqt; epilogue scatters tf32 bits into g_q/g_k/g_v
// MODE 1: A=g_att, B=g_wpt; epilogue writes fp32 C
// =====================================================================
#define GBM 128
#define GBN 128
#define GBK 32
#define NSTAGE 3
#define TILE_W    (GBM * GBK)            // words per tile (4096)
#define GEMM_SMEM_BYTES (NSTAGE * 2 * TILE_W * 4)   // 98304

template<int MODE>
__global__ void __launch_bounds__(256, 2) sgemm_tf32_v4(
    float* __restrict__ C, int M, int N, int K)
{
    extern __shared__ uint32_t sm[];
    const uint32_t sbase = smem_u32(sm);

    const uint32_t* Ap = (MODE == 1) ? g_att : g_xt;
    const uint32_t* Bw = (MODE == 1) ? g_wpt : g_wqt;

    const int tid  = threadIdx.x;
    const int warp = tid >> 5;
    const int lane = tid & 31;
    const int g    = lane >> 2;   // fragment group (0..7)
    const int q    = lane & 3;    // fragment quad-thread (0..3)

    const int bm = blockIdx.y * GBM;
    const int bn = blockIdx.x * GBN;
    const int wm = (warp >> 2) * 64;   // warp m-offset (0 or 64)
    const int wn = (warp & 3) * 32;    // warp n-offset (0,32,64,96)

    // staging ids: rows r = p*32 + srow (p=0..3), 16B chunk scc (0..7)
    const int srow = tid >> 3;          // 0..31
    const int scc  = tid & 7;           // 0..7
    uint32_t soff[4];
#pragma unroll
    for (int p = 0; p < 4; p++) {
        int r = p * 32 + srow;
        soff[p] = (uint32_t)r * GBK + (uint32_t)((scc ^ (r & 7)) * 4);
    }

    float acc[4][4][4];
#pragma unroll
    for (int i = 0; i < 4; i++)
#pragma unroll
        for (int j = 0; j < 4; j++)
#pragma unroll
            for (int e = 0; e < 4; e++) acc[i][j][e] = 0.f;

    const int NIT = K / GBK;

    // prologue: stage chunks 0 and 1 into buffers 0 and 1 (one group each)
#pragma unroll
    for (int s = 0; s < 2; s++) {
        const uint32_t dA = sbase + (uint32_t)(s * 2 * TILE_W) * 4;
        const uint32_t dB = dA + TILE_W * 4;
        const int k0 = s * GBK;
#pragma unroll
        for (int p = 0; p < 4; p++) {
            const uint32_t* as = Ap + (size_t)(bm + p * 32 + srow) * K + k0 + scc * 4;
            const uint32_t* bs = Bw + (size_t)(bn + p * 32 + srow) * K + k0 + scc * 4;
            CP_ASYNC16(dA + soff[p] * 4, as);
            CP_ASYNC16(dB + soff[p] * 4, bs);
        }
        CP_COMMIT();
    }

    for (int it = 0; it < NIT; it++) {
        // chunk `it` has landed when <=1 groups remain pending
        CP_WAIT1();
        __syncthreads();   // all warps: compute(it-1) done; chunk it visible

        // stage chunk it+2 into buffer (it+2)%3 (just freed by compute(it-1))
        if (it + 2 < NIT) {
            const int b2 = (it + 2) % NSTAGE;
            const uint32_t dA = sbase + (uint32_t)(b2 * 2 * TILE_W) * 4;
            const uint32_t dB = dA + TILE_W * 4;
            const int k0 = (it + 2) * GBK;
#pragma unroll
            for (int p = 0; p < 4; p++) {
                const uint32_t* as = Ap + (size_t)(bm + p * 32 + srow) * K + k0 + scc * 4;
                const uint32_t* bs = Bw + (size_t)(bn + p * 32 + srow) * K + k0 + scc * 4;
                CP_ASYNC16(dA + soff[p] * 4, as);
                CP_ASYNC16(dB + soff[p] * 4, bs);
            }
        }
        CP_COMMIT();   // unconditional: keeps the pending-group invariant

        // compute chunk it
        const uint32_t* As = sm + (it % NSTAGE) * 2 * TILE_W;
        const uint32_t* Bs = As + TILE_W;
#pragma unroll
        for (int ks = 0; ks < 4; ks++) {
            const int qa0 = ((2 * ks)     ^ g) * 4 + q;
            const int qa1 = ((2 * ks + 1) ^ g) * 4 + q;
            uint32_t a[4][4];
#pragma unroll
            for (int i = 0; i < 4; i++) {
                const int m0 = wm + i * 16 + g;
                a[i][0] = As[m0 * GBK + qa0];
                a[i][1] = As[(m0 + 8) * GBK + qa0];
                a[i][2] = As[m0 * GBK + qa1];
                a[i][3] = As[(m0 + 8) * GBK + qa1];
            }
#pragma unroll
            for (int j = 0; j < 4; j++) {
                const int n0 = wn + j * 8 + g;
                const uint32_t b0 = Bs[n0 * GBK + qa0];
                const uint32_t b1 = Bs[n0 * GBK + qa1];
#pragma unroll
                for (int i = 0; i < 4; i++)
                    mma_tf32(acc[i][j], a[i], b0, b1);
            }
        }
    }

    // epilogue
#pragma unroll
    for (int i = 0; i < 4; i++) {
#pragma unroll
        for (int j = 0; j < 4; j++) {
            int r0 = bm + wm + i * 16 + g;
            int n0 = bn + wn + j * 8 + 2 * q;
            if (MODE == 0) {
                int which = n0 >> 11;
                int hh    = (n0 >> 7) & (HEADS - 1);
                int d     = n0 & (HDIM - 1);
                int b     = r0 >> 11;
                uint32_t* base = (which == 0 ? g_q : which == 1 ? g_k : g_v)
                                 + ((size_t)(b * HEADS + hh)) * SEQ * HDIM;
                int s0 = r0 & (SEQ - 1);
                *(uint2*)&base[(size_t)s0 * HDIM + d] =
                    make_uint2(f2tf32(acc[i][j][0]), f2tf32(acc[i][j][1]));
                *(uint2*)&base[(size_t)(s0 + 8) * HDIM + d] =
                    make_uint2(f2tf32(acc[i][j][2]), f2tf32(acc[i][j][3]));
            } else {
                *(float2*)(C + (size_t)r0 * N + n0) =
                    make_float2(acc[i][j][0], acc[i][j][1]);
                *(float2*)(C + (size_t)(r0 + 8) * N + n0) =
                    make_float2(acc[i][j][2], acc[i][j][3]);
            }
        }
    }
}

// =====================================================================
// TF32 tensor-core flash attention (causal). All operands arrive as tf32
// bits; staging is a raw copy. Score scale applied post-MMA.
// Block = (64 q-rows, head, batch), 128 threads = 4 warps x 16-row tiles.
// =====================================================================
#define AT_BR 64
#define AT_BC 64
#define KST   132
#define PST   68
#define ATTN_SMEM_WORDS (2 * AT_BC * KST + AT_BR * PST)
#define ATTN_SMEM_BYTES (ATTN_SMEM_WORDS * 4)

__global__ void __launch_bounds__(128) attn_tf32_kernel()
{
    extern __shared__ uint32_t smw[];
    uint32_t* Ks = smw;
    uint32_t* Vs = Ks + AT_BC * KST;
    uint32_t* Ps = Vs + AT_BC * KST;

    const int t    = threadIdx.x;
    const int warp = t >> 5;
    const int lane = t & 31;
    const int g    = lane >> 2;
    const int q    = lane & 3;
    const int wrow = warp * 16;

    const int qt = blockIdx.x, h = blockIdx.y, b = blockIdx.z;
    const int q0 = qt * AT_BR;
    const size_t headBase = ((size_t)(b * HEADS + h)) * SEQ * HDIM;
    const float scale = 0.08838834764831845f;   // 1/sqrt(128)

    // stage Q tile (raw tf32 bits copy)
    {
        const uint4* Qg = (const uint4*)(g_q + headBase + (size_t)q0 * HDIM);
#pragma unroll
        for (int i = 0; i < 16; i++) {
            int idx = t + i * 128;
            int row = idx >> 5, c = idx & 31;
            *(uint4*)&Ks[row * KST + c * 4] = Qg[idx];
        }
    }
    __syncthreads();

    uint32_t qf[16][4];
#pragma unroll
    for (int ks = 0; ks < 16; ks++) {
        qf[ks][0] = Ks[(wrow + g)     * KST + ks * 8 + q];
        qf[ks][1] = Ks[(wrow + g + 8) * KST + ks * 8 + q];
        qf[ks][2] = Ks[(wrow + g)     * KST + ks * 8 + q + 4];
        qf[ks][3] = Ks[(wrow + g + 8) * KST + ks * 8 + q + 4];
    }

    float accO[16][4];
#pragma unroll
    for (int n = 0; n < 16; n++)
#pragma unroll
        for (int e = 0; e < 4; e++) accO[n][e] = 0.f;

    float m0r = -1e30f, m1r = -1e30f;
    float l0r = 0.f, l1r = 0.f;

    for (int kt = 0; kt <= qt; kt++) {
        __syncthreads();
        {
            const uint4* Kg = (const uint4*)(g_k + headBase + (size_t)(kt * AT_BC) * HDIM);
            const uint4* Vg = (const uint4*)(g_v + headBase + (size_t)(kt * AT_BC) * HDIM);
#pragma unroll
            for (int i = 0; i < 16; i++) {
                int idx = t + i * 128;
                int row = idx >> 5, c = idx & 31;
                *(uint4*)&Ks[row * KST + c * 4] = Kg[idx];
                *(uint4*)&Vs[row * KST + c * 4] = Vg[idx];
            }
        }
        __syncthreads();

        float sc[8][4];
#pragma unroll
        for (int n = 0; n < 8; n++)
#pragma unroll
            for (int e = 0; e < 4; e++) sc[n][e] = 0.f;

#pragma unroll
        for (int ks = 0; ks < 16; ks++) {
#pragma unroll
            for (int n = 0; n < 8; n++) {
                uint32_t b0 = Ks[(n * 8 + g) * KST + ks * 8 + q];
                uint32_t b1 = Ks[(n * 8 + g) * KST + ks * 8 + q + 4];
                mma_tf32(sc[n], qf[ks], b0, b1);
            }
        }

        // apply 1/sqrt(D) scale post-MMA
#pragma unroll
        for (int n = 0; n < 8; n++)
#pragma unroll
            for (int e = 0; e < 4; e++) sc[n][e] *= scale;

        if (kt == qt) {
            int r0 = wrow + g, r1 = wrow + g + 8;
#pragma unroll
            for (int n = 0; n < 8; n++) {
                int c0 = n * 8 + 2 * q, c1 = c0 + 1;
                if (c0 > r0) sc[n][0] = -1e30f;
                if (c1 > r0) sc[n][1] = -1e30f;
                if (c0 > r1) sc[n][2] = -1e30f;
                if (c1 > r1) sc[n][3] = -1e30f;
            }
        }

        float pm0 = -1e30f, pm1 = -1e30f;
#pragma unroll
        for (int n = 0; n < 8; n++) {
            pm0 = fmaxf(pm0, fmaxf(sc[n][0], sc[n][1]));
            pm1 = fmaxf(pm1, fmaxf(sc[n][2], sc[n][3]));
        }
        pm0 = fmaxf(pm0, __shfl_xor_sync(0xffffffffu, pm0, 1));
        pm0 = fmaxf(pm0, __shfl_xor_sync(0xffffffffu, pm0, 2));
        pm1 = fmaxf(pm1, __shfl_xor_sync(0xffffffffu, pm1, 1));
        pm1 = fmaxf(pm1, __shfl_xor_sync(0xffffffffu, pm1, 2));

        float mn0 = fmaxf(m0r, pm0);
        float mn1 = fmaxf(m1r, pm1);
        float al0 = __expf(m0r - mn0);
        float al1 = __expf(m1r - mn1);
        m0r = mn0; m1r = mn1;

        float ps0 = 0.f, ps1 = 0.f;
#pragma unroll
        for (int n = 0; n < 8; n++) {
            float p00 = __expf(sc[n][0] - mn0);
            float p01 = __expf(sc[n][1] - mn0);
            float p10 = __expf(sc[n][2] - mn1);
            float p11 = __expf(sc[n][3] - mn1);
            ps0 += p00 + p01;
            ps1 += p10 + p11;
            uint32_t* pr0 = &Ps[(wrow + g) * PST + n * 8 + 2 * q];
            uint32_t* pr1 = &Ps[(wrow + g + 8) * PST + n * 8 + 2 * q];
            pr0[0] = f2tf32(p00); pr0[1] = f2tf32(p01);
            pr1[0] = f2tf32(p10); pr1[1] = f2tf32(p11);
        }
        ps0 += __shfl_xor_sync(0xffffffffu, ps0, 1);
        ps0 += __shfl_xor_sync(0xffffffffu, ps0, 2);
        ps1 += __shfl_xor_sync(0xffffffffu, ps1, 1);
        ps1 += __shfl_xor_sync(0xffffffffu, ps1, 2);
        l0r = l0r * al0 + ps0;
        l1r = l1r * al1 + ps1;

#pragma unroll
        for (int n = 0; n < 16; n++) {
            accO[n][0] *= al0; accO[n][1] *= al0;
            accO[n][2] *= al1; accO[n][3] *= al1;
        }

        __syncwarp();

#pragma unroll
        for (int ks = 0; ks < 8; ks++) {
            uint32_t pa[4];
            pa[0] = Ps[(wrow + g)     * PST + ks * 8 + q];
            pa[1] = Ps[(wrow + g + 8) * PST + ks * 8 + q];
            pa[2] = Ps[(wrow + g)     * PST + ks * 8 + q + 4];
            pa[3] = Ps[(wrow + g + 8) * PST + ks * 8 + q + 4];
#pragma unroll
            for (int n = 0; n < 16; n++) {
                uint32_t b0 = Vs[(ks * 8 + q)     * KST + n * 8 + g];
                uint32_t b1 = Vs[(ks * 8 + q + 4) * KST + n * 8 + g];
                mma_tf32(accO[n], pa, b0, b1);
            }
        }
        __syncwarp();
    }

    // epilogue: normalize, write tf32 bits to g_att
    float inv0 = 1.0f / l0r;
    float inv1 = 1.0f / l1r;
    size_t row0 = (size_t)(b * SEQ + q0 + wrow + g);
    size_t row1 = row0 + 8;
#pragma unroll
    for (int n = 0; n < 16; n++) {
        int d = n * 8 + 2 * q;
        *(uint2*)&g_att[row0 * EMB + h * HDIM + d] =
            make_uint2(f2tf32(accO[n][0] * inv0), f2tf32(accO[n][1] * inv0));
        *(uint2*)&g_att[row1 * EMB + h * HDIM + d] =
            make_uint2(f2tf32(accO[n][2] * inv1), f2tf32(accO[n][3] * inv1));
    }
}

// =====================================================================
// launch
// =====================================================================
extern "C" void kernel_launch(void* const* d_in, const int* in_sizes, int n_in,
                              void* d_out, int out_size)
{
    (void)in_sizes; (void)n_in; (void)out_size;
    const float* x     = (const float*)d_in[0];   // [B,S,E]
    const float* Wqkv  = (const float*)d_in[1];   // [3E,E]
    const float* Wproj = (const float*)d_in[2];   // [E,E]
    float* out = (float*)d_out;                   // [B,S,E]

    cudaFuncSetAttribute(sgemm_tf32_v4<0>,
                         cudaFuncAttributeMaxDynamicSharedMemorySize,
                         GEMM_SMEM_BYTES);
    cudaFuncSetAttribute(sgemm_tf32_v4<1>,
                         cudaFuncAttributeMaxDynamicSharedMemorySize,
                         GEMM_SMEM_BYTES);
    cudaFuncSetAttribute(attn_tf32_kernel,
                         cudaFuncAttributeMaxDynamicSharedMemorySize,
                         ATTN_SMEM_BYTES);

    // 0) prepass: fp32 -> tf32 bit buffers
    cvt_tf32_kernel<0><<<1024, 256>>>(x,     MROWS * EMB);
    cvt_tf32_kernel<1><<<1024, 256>>>(Wqkv,  EMB3 * EMB);
    cvt_tf32_kernel<2><<<1024, 256>>>(Wproj, EMB * EMB);

    // 1) qkv = x @ Wqkv^T -> g_q/g_k/g_v (tf32 bits, [B,H,S,D])
    dim3 g1(EMB3 / GBN, MROWS / GBM);
    sgemm_tf32_v4<0><<<g1, 256, GEMM_SMEM_BYTES>>>(nullptr, MROWS, EMB3, EMB);

    // 2) causal flash attention -> g_att (tf32 bits, [B,S,E])
    dim3 g2(SEQ / AT_BR, HEADS, BATCH);
    attn_tf32_kernel<<<g2, 128, ATTN_SMEM_BYTES>>>();

    // 3) out = g_att @ Wproj^T (fp32 out)
    dim3 g3(EMB / GBN, MROWS / GBM);
    sgemm_tf32_v4<1><<<g3, 256, GEMM_SMEM_BYTES>>>(out, MROWS, EMB, EMB);
}